// round 7
// baseline (speedup 1.0000x reference)
#include <cuda_runtime.h>
#include <math.h>
#include <stdint.h>

// Problem constants
#define NTOK 4096          // B*T = 2*2048
#define CDIM 1024          // n_embed
#define NEXP 8
#define DFF  4096
#define CAP  1024          // NTOK*2/8
#define NHEADS 16
#define HD   64
#define TSEQ 2048
#define BSZ  2

// GEMM pipeline shared-memory layout (floats):
//   As: 3 stages x 128 rows x 20 (16 k + 4 pad)   = 3*2560
//   Bs: 3 stages x 16 rows x 136 (128 n + 8 pad)  = 3*2176
#define AS_STRIDE 20
#define BS_STRIDE 136
#define AS_STAGE  2560
#define BS_STAGE  2176
#define BS_OFF    7680          // 3 * AS_STAGE
#define SMEM_WORDS (BS_OFF + 3 * BS_STAGE)
#define SMEM_BYTES (SMEM_WORDS * 4)

// ---------------- scratch (device globals; no allocations) ----------------
__device__ float g_h1   [NTOK * CDIM];
__device__ float g_qkv  [NTOK * 3 * CDIM];
__device__ float g_attn [NTOK * CDIM];     // permuted pre-projection activation
__device__ float g_x2   [NTOK * CDIM];     // x + attn_proj
__device__ float g_h2   [NTOK * CDIM];     // ln2(x2)
__device__ float g_logits [NTOK * NEXP];
__device__ float g_nlogits[NTOK * NEXP];
__device__ int   g_sel  [NTOK];            // e0 | (e1<<8)
__device__ float g_gate [NTOK * 2];
__device__ int   g_slot_idx [NEXP * CAP];
__device__ float g_slot_gate[NEXP * CAP];
__device__ float g_zero[CDIM];
__device__ float g_hid [(size_t)NEXP * CAP * DFF];
__device__ float g_upd [NTOK * CDIM];
__device__ float g_ent;

// ---------------- helpers ----------------
__device__ __forceinline__ float ftf(float x) {
    float r;
    asm("cvt.rna.tf32.f32 %0, %1;" : "=f"(r) : "f"(x));
    return r;
}

__device__ __forceinline__ void mma_tf32(float c[4], const uint32_t a[4], const uint32_t b[2]) {
    asm volatile(
        "mma.sync.aligned.m16n8k8.row.col.f32.tf32.tf32.f32 "
        "{%0,%1,%2,%3},{%4,%5,%6,%7},{%8,%9},{%0,%1,%2,%3};"
        : "+f"(c[0]), "+f"(c[1]), "+f"(c[2]), "+f"(c[3])
        : "r"(a[0]), "r"(a[1]), "r"(a[2]), "r"(a[3]), "r"(b[0]), "r"(b[1]));
}

// ---------------- zero scratch ----------------
__global__ void zero_kernel() {
    size_t i = (size_t)blockIdx.x * blockDim.x + threadIdx.x;
    ((float4*)g_upd)[i] = make_float4(0.f, 0.f, 0.f, 0.f);
    if (i < CDIM / 4) ((float4*)g_zero)[i] = make_float4(0.f, 0.f, 0.f, 0.f);
    if (i == 0) g_ent = 0.f;
}

// ---------------- layernorm (1 block per row, 256 threads) ----------------
__global__ __launch_bounds__(256) void ln_kernel(const float* __restrict__ x,
                                                 const float* __restrict__ gam,
                                                 const float* __restrict__ bet,
                                                 float* __restrict__ out) {
    __shared__ float red[8];
    __shared__ float s_mu, s_rs;
    int row = blockIdx.x, tid = threadIdx.x;
    const float* xr = x + (size_t)row * CDIM;
    float v[4];
    float s = 0.f;
#pragma unroll
    for (int i = 0; i < 4; i++) { v[i] = xr[tid + i * 256]; s += v[i]; }
    for (int o = 16; o; o >>= 1) s += __shfl_xor_sync(~0u, s, o);
    if ((tid & 31) == 0) red[tid >> 5] = s;
    __syncthreads();
    if (tid < 8) {
        float t = red[tid];
        for (int o = 4; o; o >>= 1) t += __shfl_xor_sync(0xffu, t, o);
        if (tid == 0) s_mu = t * (1.f / CDIM);
    }
    __syncthreads();
    float mu = s_mu;
    float s2 = 0.f;
#pragma unroll
    for (int i = 0; i < 4; i++) { float d = v[i] - mu; s2 += d * d; }
    for (int o = 16; o; o >>= 1) s2 += __shfl_xor_sync(~0u, s2, o);
    if ((tid & 31) == 0) red[tid >> 5] = s2;
    __syncthreads();
    if (tid < 8) {
        float t = red[tid];
        for (int o = 4; o; o >>= 1) t += __shfl_xor_sync(0xffu, t, o);
        if (tid == 0) s_rs = rsqrtf(t * (1.f / CDIM) + 1e-5f);
    }
    __syncthreads();
    float rs = s_rs;
    float* orow = out + (size_t)row * CDIM;
#pragma unroll
    for (int i = 0; i < 4; i++) {
        int c = tid + i * 256;
        orow[c] = (v[i] - mu) * rs * gam[c] + bet[c];
    }
}

// ---------------- tf32 tensor-core GEMM 128x128x16, 3-stage cp.async ----------------
// EPI: 0 = store (+bias), 1 = store relu(+bias), 2 = store + residual,
//      3 = gated atomic scatter into scat[] using slot tables (bias added first)
// GATHER: A rows indirected through sidx (invalid -> zero row)
template <int EPI, bool GATHER>
__global__ __launch_bounds__(256) void tgemm2_kernel(
    const float* __restrict__ A, const float* __restrict__ B, float* __restrict__ Cout,
    int M, int N, int K,
    const float* __restrict__ bias, const float* __restrict__ res,
    const int* __restrict__ sidx, const float* __restrict__ sgate,
    float* __restrict__ scat, const float* __restrict__ zrow,
    size_t sA, size_t sB, size_t sC, int sBias)
{
    extern __shared__ float dsm[];
    __shared__ const float* arow[128];

    const int z = blockIdx.z;
    if (!GATHER) A += (size_t)z * sA;
    B += (size_t)z * sB;
    if (Cout) Cout += (size_t)z * sC;
    if (bias) bias += (size_t)z * sBias;

    const int tid  = threadIdx.x;
    const int lane = tid & 31, wid = tid >> 5;
    const int wr = wid >> 2, wc = wid & 3;      // warp tile: 64(M) x 32(N)
    const int tg = lane >> 2, tq = lane & 3;

    if (tid < 128) {
        const float* p;
        if (GATHER) {
            int idx = sidx[z * M + blockIdx.y * 128 + tid];
            p = (idx >= 0) ? (A + (size_t)idx * K) : zrow;
        } else {
            p = A + (size_t)(blockIdx.y * 128 + tid) * K;
        }
        arow[tid] = p;
    }
    __syncthreads();

    const uint32_t sbase = (uint32_t)__cvta_generic_to_shared(dsm);
    const float* Bbase = B + blockIdx.x * 128;

#define ISSUE(st, k0)                                                          \
    do {                                                                       \
        _Pragma("unroll")                                                      \
        for (int c2 = 0; c2 < 2; c2++) {                                       \
            int cc_ = tid + c2 * 256;                                          \
            int row_ = cc_ >> 2, kq_ = (cc_ & 3) << 2;                         \
            uint32_t d_ = sbase + (uint32_t)(((st) * AS_STAGE + row_ * AS_STRIDE + kq_) * 4); \
            asm volatile("cp.async.cg.shared.global [%0], [%1], 16;\n"         \
                         :: "r"(d_), "l"(arow[row_] + (k0) + kq_));            \
        }                                                                      \
        _Pragma("unroll")                                                      \
        for (int c2 = 0; c2 < 2; c2++) {                                       \
            int cc_ = tid + c2 * 256;                                          \
            int row_ = cc_ >> 5, col_ = (cc_ & 31) << 2;                       \
            uint32_t d_ = sbase + (uint32_t)((BS_OFF + (st) * BS_STAGE + row_ * BS_STRIDE + col_) * 4); \
            asm volatile("cp.async.cg.shared.global [%0], [%1], 16;\n"         \
                         :: "r"(d_), "l"(Bbase + (size_t)((k0) + row_) * N + col_)); \
        }                                                                      \
    } while (0)

    float c[4][4][4];
#pragma unroll
    for (int i = 0; i < 4; i++)
#pragma unroll
        for (int j = 0; j < 4; j++)
#pragma unroll
            for (int q = 0; q < 4; q++) c[i][j][q] = 0.f;

    const int KT = K >> 4;
    ISSUE(0, 0);
    asm volatile("cp.async.commit_group;\n");
    ISSUE(1, 16);
    asm volatile("cp.async.commit_group;\n");

    for (int it = 0; it < KT; it++) {
        asm volatile("cp.async.wait_group 1;\n");
        __syncthreads();
        if (it + 2 < KT) {
            int stn = (it + 2) % 3;
            ISSUE(stn, (it + 2) * 16);
        }
        asm volatile("cp.async.commit_group;\n");

        const int st = it % 3;
        const float* As = dsm + st * AS_STAGE;
        const float* Bs = dsm + BS_OFF + st * BS_STAGE;
#pragma unroll
        for (int kk = 0; kk < 16; kk += 8) {
            uint32_t af[4][4], bf[4][2];
#pragma unroll
            for (int mi = 0; mi < 4; mi++) {
                int m0 = wr * 64 + mi * 16 + tg;
                af[mi][0] = __float_as_uint(As[m0 * AS_STRIDE + kk + tq]);
                af[mi][1] = __float_as_uint(As[(m0 + 8) * AS_STRIDE + kk + tq]);
                af[mi][2] = __float_as_uint(As[m0 * AS_STRIDE + kk + tq + 4]);
                af[mi][3] = __float_as_uint(As[(m0 + 8) * AS_STRIDE + kk + tq + 4]);
            }
#pragma unroll
            for (int ni = 0; ni < 4; ni++) {
                int n0 = wc * 32 + ni * 8 + tg;
                bf[ni][0] = __float_as_uint(Bs[(kk + tq) * BS_STRIDE + n0]);
                bf[ni][1] = __float_as_uint(Bs[(kk + tq + 4) * BS_STRIDE + n0]);
            }
#pragma unroll
            for (int mi = 0; mi < 4; mi++)
#pragma unroll
                for (int ni = 0; ni < 4; ni++)
                    mma_tf32(c[mi][ni], af[mi], bf[ni]);
        }
    }
#undef ISSUE

    // epilogue
#pragma unroll
    for (int mi = 0; mi < 4; mi++) {
        int r0 = blockIdx.y * 128 + wr * 64 + mi * 16 + tg;
        int r1 = r0 + 8;
#pragma unroll
        for (int ni = 0; ni < 4; ni++) {
            int cc = blockIdx.x * 128 + wc * 32 + ni * 8 + tq * 2;
            float v00 = c[mi][ni][0], v01 = c[mi][ni][1];
            float v10 = c[mi][ni][2], v11 = c[mi][ni][3];
            if (bias) {
                float b0v = bias[cc], b1v = bias[cc + 1];
                v00 += b0v; v01 += b1v; v10 += b0v; v11 += b1v;
            }
            if (EPI == 1) {
                v00 = fmaxf(v00, 0.f); v01 = fmaxf(v01, 0.f);
                v10 = fmaxf(v10, 0.f); v11 = fmaxf(v11, 0.f);
            }
            if (EPI == 2) {
                float2 e0 = *(const float2*)&res[(size_t)r0 * N + cc];
                float2 e1 = *(const float2*)&res[(size_t)r1 * N + cc];
                v00 += e0.x; v01 += e0.y; v10 += e1.x; v11 += e1.y;
            }
            if (EPI == 3) {
                int gs0 = z * M + r0, gs1 = z * M + r1;
                int i0 = sidx[gs0], i1 = sidx[gs1];
                if (i0 >= 0) {
                    float g = sgate[gs0];
                    atomicAdd(&scat[(size_t)i0 * N + cc],     g * v00);
                    atomicAdd(&scat[(size_t)i0 * N + cc + 1], g * v01);
                }
                if (i1 >= 0) {
                    float g = sgate[gs1];
                    atomicAdd(&scat[(size_t)i1 * N + cc],     g * v10);
                    atomicAdd(&scat[(size_t)i1 * N + cc + 1], g * v11);
                }
            } else {
                *(float2*)&Cout[(size_t)r0 * N + cc] = make_float2(v00, v01);
                *(float2*)&Cout[(size_t)r1 * N + cc] = make_float2(v10, v11);
            }
        }
    }
}

// ---------------- tensor-core flash attention ----------------
// Block: 128 queries x one (b,h). 8 warps, each 16 query rows x full 64 head dim.
// K/V staged in smem (stride 72 -> conflict-free for both access patterns).
__global__ __launch_bounds__(256) void attn_tc_kernel(const float* __restrict__ qkv,
                                                      float* __restrict__ aout) {
    __shared__ float Ks[64][72];
    __shared__ float Vs[64][72];
    const int bh = blockIdx.y;
    const int b = bh >> 4, h = bh & 15;
    const int tid = threadIdx.x, lane = tid & 31, w = tid >> 5;
    const int tg = lane >> 2, tq = lane & 3;
    const int q0 = blockIdx.x * 128 + w * 16;

    const float* qbase = qkv + (size_t)b * TSEQ * 3072 + h * 64;

    // Q a-fragments, scale folded in, tf32-converted, register-resident
    uint32_t qa[8][4];
    {
        const float* qr0 = qbase + (size_t)(q0 + tg) * 3072;
        const float* qr1 = qbase + (size_t)(q0 + tg + 8) * 3072;
#pragma unroll
        for (int kk = 0; kk < 8; kk++) {
            qa[kk][0] = __float_as_uint(ftf(qr0[kk * 8 + tq]     * 0.125f));
            qa[kk][1] = __float_as_uint(ftf(qr1[kk * 8 + tq]     * 0.125f));
            qa[kk][2] = __float_as_uint(ftf(qr0[kk * 8 + tq + 4] * 0.125f));
            qa[kk][3] = __float_as_uint(ftf(qr1[kk * 8 + tq + 4] * 0.125f));
        }
    }

    float oacc[8][4];
#pragma unroll
    for (int dt = 0; dt < 8; dt++)
#pragma unroll
        for (int i = 0; i < 4; i++) oacc[dt][i] = 0.f;
    float m0 = -1e30f, m1 = -1e30f, l0 = 0.f, l1 = 0.f;

    const float* kbase = qbase + 1024;
    const float* vbase = qbase + 2048;
    const int slo = (tg << 2) + (tq >> 1);
    const int shi = slo + 2;

    for (int s0 = 0; s0 < TSEQ; s0 += 64) {
        __syncthreads();
        for (int i = tid; i < 64 * 16; i += 256) {
            int j = i >> 4, dv = (i & 15) << 2;
            float4 kv = *(const float4*)(kbase + (size_t)(s0 + j) * 3072 + dv);
            float4 vv = *(const float4*)(vbase + (size_t)(s0 + j) * 3072 + dv);
            Ks[j][dv] = ftf(kv.x); Ks[j][dv + 1] = ftf(kv.y);
            Ks[j][dv + 2] = ftf(kv.z); Ks[j][dv + 3] = ftf(kv.w);
            Vs[j][dv] = ftf(vv.x); Vs[j][dv + 1] = ftf(vv.y);
            Vs[j][dv + 2] = ftf(vv.z); Vs[j][dv + 3] = ftf(vv.w);
        }
        __syncthreads();

        // S = Q * K^T  (per warp: 16 x 64)
        float s[8][4];
#pragma unroll
        for (int nt = 0; nt < 8; nt++) {
            s[nt][0] = s[nt][1] = s[nt][2] = s[nt][3] = 0.f;
#pragma unroll
            for (int kk = 0; kk < 8; kk++) {
                uint32_t bb[2] = {
                    __float_as_uint(Ks[nt * 8 + tg][kk * 8 + tq]),
                    __float_as_uint(Ks[nt * 8 + tg][kk * 8 + tq + 4])};
                mma_tf32(s[nt], qa[kk], bb);
            }
        }

        // online softmax (rows tg / tg+8, spread over lanes slo group)
        float rm0 = -1e30f, rm1 = -1e30f;
#pragma unroll
        for (int nt = 0; nt < 8; nt++) {
            rm0 = fmaxf(rm0, fmaxf(s[nt][0], s[nt][1]));
            rm1 = fmaxf(rm1, fmaxf(s[nt][2], s[nt][3]));
        }
        rm0 = fmaxf(rm0, __shfl_xor_sync(~0u, rm0, 1));
        rm0 = fmaxf(rm0, __shfl_xor_sync(~0u, rm0, 2));
        rm1 = fmaxf(rm1, __shfl_xor_sync(~0u, rm1, 1));
        rm1 = fmaxf(rm1, __shfl_xor_sync(~0u, rm1, 2));
        float mn0 = fmaxf(m0, rm0), mn1 = fmaxf(m1, rm1);
        float sc0 = __expf(m0 - mn0), sc1 = __expf(m1 - mn1);
        m0 = mn0; m1 = mn1;
        float rs0 = 0.f, rs1 = 0.f;
#pragma unroll
        for (int nt = 0; nt < 8; nt++) {
            s[nt][0] = __expf(s[nt][0] - mn0);
            s[nt][1] = __expf(s[nt][1] - mn0);
            s[nt][2] = __expf(s[nt][2] - mn1);
            s[nt][3] = __expf(s[nt][3] - mn1);
            rs0 += s[nt][0] + s[nt][1];
            rs1 += s[nt][2] + s[nt][3];
        }
        rs0 += __shfl_xor_sync(~0u, rs0, 1);
        rs0 += __shfl_xor_sync(~0u, rs0, 2);
        rs1 += __shfl_xor_sync(~0u, rs1, 1);
        rs1 += __shfl_xor_sync(~0u, rs1, 2);
        l0 = l0 * sc0 + rs0;
        l1 = l1 * sc1 + rs1;
#pragma unroll
        for (int dt = 0; dt < 8; dt++) {
            oacc[dt][0] *= sc0; oacc[dt][1] *= sc0;
            oacc[dt][2] *= sc1; oacc[dt][3] *= sc1;
        }

        // O += P * V   (P C-frag -> A-frag relayout via shuffles)
#pragma unroll
        for (int kk = 0; kk < 8; kk++) {
            uint32_t pa[4];
            float e, o;
            e = __shfl_sync(~0u, s[kk][0], slo); o = __shfl_sync(~0u, s[kk][1], slo);
            pa[0] = __float_as_uint((tq & 1) ? o : e);
            e = __shfl_sync(~0u, s[kk][2], slo); o = __shfl_sync(~0u, s[kk][3], slo);
            pa[1] = __float_as_uint((tq & 1) ? o : e);
            e = __shfl_sync(~0u, s[kk][0], shi); o = __shfl_sync(~0u, s[kk][1], shi);
            pa[2] = __float_as_uint((tq & 1) ? o : e);
            e = __shfl_sync(~0u, s[kk][2], shi); o = __shfl_sync(~0u, s[kk][3], shi);
            pa[3] = __float_as_uint((tq & 1) ? o : e);
#pragma unroll
            for (int dt = 0; dt < 8; dt++) {
                uint32_t bb[2] = {
                    __float_as_uint(Vs[kk * 8 + tq][dt * 8 + tg]),
                    __float_as_uint(Vs[kk * 8 + tq + 4][dt * 8 + tg])};
                mma_tf32(oacc[dt], pa, bb);
            }
        }
    }

    // finalize + permuted store: out[(t&31)*64+d][h*64 + (t>>5)]
    float inv0 = 1.f / l0, inv1 = 1.f / l1;
    float* ab = aout + (size_t)b * TSEQ * CDIM;
    int t0 = q0 + tg, t1 = t0 + 8;
    int c0 = h * 64 + (t0 >> 5), r0b = (t0 & 31) * 64;
    int c1 = h * 64 + (t1 >> 5), r1b = (t1 & 31) * 64;
#pragma unroll
    for (int dt = 0; dt < 8; dt++) {
        int d = dt * 8 + tq * 2;
        ab[(size_t)(r0b + d) * CDIM + c0]     = oacc[dt][0] * inv0;
        ab[(size_t)(r0b + d + 1) * CDIM + c0] = oacc[dt][1] * inv0;
        ab[(size_t)(r1b + d) * CDIM + c1]     = oacc[dt][2] * inv1;
        ab[(size_t)(r1b + d + 1) * CDIM + c1] = oacc[dt][3] * inv1;
    }
}

// ---------------- routing GEMV (warp per token) ----------------
__global__ __launch_bounds__(256) void route_kernel(const float* __restrict__ wr,
                                                    const float* __restrict__ br,
                                                    const float* __restrict__ wn,
                                                    const float* __restrict__ bn) {
    int warp = threadIdx.x >> 5, lane = threadIdx.x & 31;
    int n = blockIdx.x * 8 + warp;
    const float* hp = g_h2 + (size_t)n * CDIM;
    float pr[8], pn[8];
#pragma unroll
    for (int e = 0; e < 8; e++) { pr[e] = 0.f; pn[e] = 0.f; }
    for (int c = lane; c < CDIM; c += 32) {
        float hv = hp[c];
#pragma unroll
        for (int e = 0; e < 8; e++) {
            pr[e] += hv * wr[c * 8 + e];
            pn[e] += hv * wn[c * 8 + e];
        }
    }
#pragma unroll
    for (int e = 0; e < 8; e++) {
        for (int o = 16; o; o >>= 1) {
            pr[e] += __shfl_xor_sync(~0u, pr[e], o);
            pn[e] += __shfl_xor_sync(~0u, pn[e], o);
        }
    }
    if (lane == 0) {
#pragma unroll
        for (int e = 0; e < 8; e++) {
            g_logits[n * 8 + e]  = pr[e] + br[e];
            g_nlogits[n * 8 + e] = pn[e] + bn[e];
        }
    }
}

// ---------------- per-token routing epilogue + entropy ----------------
__global__ __launch_bounds__(256) void route_post_kernel(const float* __restrict__ noise) {
    __shared__ float red[8];
    int n = blockIdx.x * blockDim.x + threadIdx.x;
    float noisy[8];
    float mx = -1e30f;
#pragma unroll
    for (int e = 0; e < 8; e++) {
        float nl = g_nlogits[n * 8 + e];
        float sp = log1pf(expf(-fabsf(nl))) + fmaxf(nl, 0.f);   // softplus
        float v = g_logits[n * 8 + e] + noise[n * 8 + e] * sp;
        noisy[e] = v;
        mx = fmaxf(mx, v);
    }
    float s = 0.f, p[8];
#pragma unroll
    for (int e = 0; e < 8; e++) { p[e] = expf(noisy[e] - mx); s += p[e]; }
    float inv = 1.f / s, ent = 0.f;
#pragma unroll
    for (int e = 0; e < 8; e++) { float pe = p[e] * inv; ent -= pe * logf(pe + 1e-8f); }

    int i0 = 0;
#pragma unroll
    for (int e = 1; e < 8; e++) if (noisy[e] > noisy[i0]) i0 = e;
    int i1 = (i0 == 0) ? 1 : 0;
#pragma unroll
    for (int e = 0; e < 8; e++) if (e != i0 && noisy[e] > noisy[i1]) i1 = e;
    float dgl = expf(noisy[i1] - noisy[i0]);
    float g0 = 1.f / (1.f + dgl);
    float g1 = dgl * g0;
    g_sel[n] = i0 | (i1 << 8);
    g_gate[2 * n] = g0;
    g_gate[2 * n + 1] = g1;

    float es = ent;
    for (int o = 16; o; o >>= 1) es += __shfl_xor_sync(~0u, es, o);
    int lane = threadIdx.x & 31, wid = threadIdx.x >> 5;
    if (lane == 0) red[wid] = es;
    __syncthreads();
    if (threadIdx.x < 8) {
        float t = red[threadIdx.x];
        for (int o = 4; o; o >>= 1) t += __shfl_xor_sync(0xffu, t, o);
        if (threadIdx.x == 0) atomicAdd(&g_ent, t);
    }
}

// ---------------- ordered capacity assignment (1 warp, ballot scan) ----------------
__global__ void assign_kernel() {
    int lane = threadIdx.x;
    int cnt[8];
#pragma unroll
    for (int e = 0; e < 8; e++) cnt[e] = 0;
    unsigned lt = (1u << lane) - 1u;
    for (int n0 = 0; n0 < NTOK; n0 += 32) {
        int n = n0 + lane;
        int sel = g_sel[n];
        int e0 = sel & 255, e1 = (sel >> 8) & 255;
        float g0 = g_gate[2 * n], g1 = g_gate[2 * n + 1];
#pragma unroll
        for (int e = 0; e < 8; e++) {
            bool mt = (e0 == e) || (e1 == e);
            unsigned mask = __ballot_sync(~0u, mt);
            if (mt) {
                int r = cnt[e] + __popc(mask & lt);
                if (r < CAP) {
                    g_slot_idx[e * CAP + r]  = n;
                    g_slot_gate[e * CAP + r] = (e0 == e) ? g0 : g1;
                }
            }
            cnt[e] += __popc(mask);
        }
    }
#pragma unroll
    for (int e = 0; e < 8; e++) {
        for (int r = cnt[e] + lane; r < CAP; r += 32) {
            g_slot_idx[e * CAP + r]  = -1;
            g_slot_gate[e * CAP + r] = 0.f;
        }
    }
}

// ---------------- final: out = x2 + updates ; tail = entropy/N ----------------
__global__ void final_kernel(float* __restrict__ out, int out_size) {
    int i = blockIdx.x * blockDim.x + threadIdx.x;
    if (i < NTOK * CDIM) out[i] = g_x2[i] + g_upd[i];
    else if (i < out_size) out[i] = g_ent * (1.f / NTOK);
}

// ---------------- host launcher ----------------
static float* symf(const void* s) { void* p = nullptr; cudaGetSymbolAddress(&p, s); return (float*)p; }
static int*   symi(const void* s) { void* p = nullptr; cudaGetSymbolAddress(&p, s); return (int*)p; }

extern "C" void kernel_launch(void* const* d_in, const int* in_sizes, int n_in,
                              void* d_out, int out_size) {
    const float* x       = (const float*)d_in[0];
    const float* noise   = (const float*)d_in[1];
    const float* gamma1  = (const float*)d_in[2];
    const float* beta1   = (const float*)d_in[3];
    const float* gamma2  = (const float*)d_in[4];
    const float* beta2   = (const float*)d_in[5];
    const float* w_qkv   = (const float*)d_in[6];
    const float* w_out   = (const float*)d_in[7];
    const float* w_route = (const float*)d_in[8];
    const float* b_route = (const float*)d_in[9];
    const float* w_noise = (const float*)d_in[10];
    const float* b_noise = (const float*)d_in[11];
    const float* w1      = (const float*)d_in[12];
    const float* b1      = (const float*)d_in[13];
    const float* w2      = (const float*)d_in[14];
    const float* b2      = (const float*)d_in[15];
    float* out = (float*)d_out;

    float* p_h1   = symf(g_h1);
    float* p_qkv  = symf(g_qkv);
    float* p_attn = symf(g_attn);
    float* p_x2   = symf(g_x2);
    float* p_h2   = symf(g_h2);
    float* p_hid  = symf(g_hid);
    float* p_upd  = symf(g_upd);
    float* p_zero = symf(g_zero);
    int*   p_sidx = symi(g_slot_idx);
    float* p_sg   = symf(g_slot_gate);

    static int smem_set = 0;
    if (!smem_set) {
        cudaFuncSetAttribute(tgemm2_kernel<0, false>, cudaFuncAttributeMaxDynamicSharedMemorySize, SMEM_BYTES);
        cudaFuncSetAttribute(tgemm2_kernel<2, false>, cudaFuncAttributeMaxDynamicSharedMemorySize, SMEM_BYTES);
        cudaFuncSetAttribute(tgemm2_kernel<1, true>,  cudaFuncAttributeMaxDynamicSharedMemorySize, SMEM_BYTES);
        cudaFuncSetAttribute(tgemm2_kernel<3, false>, cudaFuncAttributeMaxDynamicSharedMemorySize, SMEM_BYTES);
        smem_set = 1;
    }

    // 0) zero updates + zero-row + entropy
    zero_kernel<<<NTOK * CDIM / 4 / 256, 256>>>();
    // 1) ln1
    ln_kernel<<<NTOK, 256>>>(x, gamma1, beta1, p_h1);
    // 2) qkv = h1 @ w_qkv  [4096 x 3072 x 1024]
    tgemm2_kernel<0, false><<<dim3(3072 / 128, 4096 / 128, 1), 256, SMEM_BYTES>>>(
        p_h1, w_qkv, p_qkv, 4096, 3072, 1024,
        nullptr, nullptr, nullptr, nullptr, nullptr, p_zero, 0, 0, 0, 0);
    // 3) tensor-core flash attention -> permuted activation
    attn_tc_kernel<<<dim3(TSEQ / 128, BSZ * NHEADS), 256>>>(p_qkv, p_attn);
    // 4) x2 = x + attn @ w_out  [4096 x 1024 x 1024]
    tgemm2_kernel<2, false><<<dim3(1024 / 128, 4096 / 128, 1), 256, SMEM_BYTES>>>(
        p_attn, w_out, p_x2, 4096, 1024, 1024,
        nullptr, x, nullptr, nullptr, nullptr, p_zero, 0, 0, 0, 0);
    // 5) ln2
    ln_kernel<<<NTOK, 256>>>(p_x2, gamma2, beta2, p_h2);
    // 6) routing GEMV
    route_kernel<<<NTOK / 8, 256>>>(w_route, b_route, w_noise, b_noise);
    // 7) routing epilogue (noisy top-2, gates, entropy)
    route_post_kernel<<<NTOK / 256, 256>>>(noise);
    // 8) ordered capacity assignment
    assign_kernel<<<1, 32>>>();
    // 9) hid = relu(h2[slot] @ w1 + b1)  per expert [1024 x 4096 x 1024], fused gather
    tgemm2_kernel<1, true><<<dim3(4096 / 128, 1024 / 128, NEXP), 256, SMEM_BYTES>>>(
        p_h2, w1, p_hid, 1024, 4096, 1024,
        b1, nullptr, p_sidx, nullptr, nullptr, p_zero,
        0, (size_t)CDIM * DFF, (size_t)CAP * DFF, DFF);
    // 10) yo = hid @ w2 + b2, gated atomic scatter into updates [1024 x 1024 x 4096]
    tgemm2_kernel<3, false><<<dim3(1024 / 128, 1024 / 128, NEXP), 256, SMEM_BYTES>>>(
        p_hid, w2, nullptr, 1024, 1024, 4096,
        b2, nullptr, p_sidx, p_sg, p_upd, p_zero,
        (size_t)CAP * DFF, (size_t)DFF * CDIM, 0, CDIM);
    // 11) final add + entropy tail
    final_kernel<<<(out_size + 255) / 256, 256>>>(out, out_size);
}

// round 9
// speedup vs baseline: 1.0675x; 1.0675x over previous
#include <cuda_runtime.h>
#include <math.h>
#include <stdint.h>

#define NTOK 4096
#define CDIM 1024
#define NEXP 8
#define DFF  4096
#define CAP  1024
#define TSEQ 2048
#define BSZ  2

// tgemm3: 128x128 tile, BK=32, 2 stages
#define A3_STRIDE 36
#define B3_STRIDE 136
#define A3_STAGE  4608      // 128*36
#define B3_STAGE  4352      // 32*136
#define B3_OFF    9216      // 2*A3_STAGE
#define SMEM3_BYTES ((B3_OFF + 2 * B3_STAGE) * 4)   // 71680

__device__ float g_h1   [NTOK * CDIM];
__device__ float g_qkv  [NTOK * 3 * CDIM];
__device__ float g_attn [NTOK * CDIM];
__device__ float g_x2   [NTOK * CDIM];
__device__ float g_h2   [NTOK * CDIM];
__device__ float g_logits [NTOK * NEXP];
__device__ float g_nlogits[NTOK * NEXP];
__device__ int   g_sel  [NTOK];
__device__ float g_gate [NTOK * 2];
__device__ int   g_slot_idx [NEXP * CAP];
__device__ float g_slot_gate[NEXP * CAP];
__device__ float g_zero[CDIM];
__device__ float g_hid [(size_t)NEXP * CAP * DFF];
__device__ float g_upd [NTOK * CDIM];
__device__ float g_ent;

__device__ __forceinline__ float ftf(float x) {
    float r; asm("cvt.rna.tf32.f32 %0, %1;" : "=f"(r) : "f"(x)); return r;
}
__device__ __forceinline__ void mma_tf32(float c[4], const uint32_t a[4], const uint32_t b[2]) {
    asm volatile("mma.sync.aligned.m16n8k8.row.col.f32.tf32.tf32.f32 "
        "{%0,%1,%2,%3},{%4,%5,%6,%7},{%8,%9},{%0,%1,%2,%3};"
        : "+f"(c[0]), "+f"(c[1]), "+f"(c[2]), "+f"(c[3])
        : "r"(a[0]), "r"(a[1]), "r"(a[2]), "r"(a[3]), "r"(b[0]), "r"(b[1]));
}

__global__ void zero_kernel() {
    size_t i = (size_t)blockIdx.x * blockDim.x + threadIdx.x;
    ((float4*)g_upd)[i] = make_float4(0.f, 0.f, 0.f, 0.f);
    if (i < CDIM / 4) ((float4*)g_zero)[i] = make_float4(0.f, 0.f, 0.f, 0.f);
    if (i == 0) g_ent = 0.f;
}

__global__ __launch_bounds__(256) void ln_kernel(const float* __restrict__ x,
                                                 const float* __restrict__ gam,
                                                 const float* __restrict__ bet,
                                                 float* __restrict__ out) {
    __shared__ float red[8];
    __shared__ float s_mu, s_rs;
    int row = blockIdx.x, tid = threadIdx.x;
    const float* xr = x + (size_t)row * CDIM;
    float v[4]; float s = 0.f;
#pragma unroll
    for (int i = 0; i < 4; i++) { v[i] = xr[tid + i * 256]; s += v[i]; }
    for (int o = 16; o; o >>= 1) s += __shfl_xor_sync(~0u, s, o);
    if ((tid & 31) == 0) red[tid >> 5] = s;
    __syncthreads();
    if (tid < 8) {
        float t = red[tid];
        for (int o = 4; o; o >>= 1) t += __shfl_xor_sync(0xffu, t, o);
        if (tid == 0) s_mu = t * (1.f / CDIM);
    }
    __syncthreads();
    float mu = s_mu, s2 = 0.f;
#pragma unroll
    for (int i = 0; i < 4; i++) { float d = v[i] - mu; s2 += d * d; }
    for (int o = 16; o; o >>= 1) s2 += __shfl_xor_sync(~0u, s2, o);
    if ((tid & 31) == 0) red[tid >> 5] = s2;
    __syncthreads();
    if (tid < 8) {
        float t = red[tid];
        for (int o = 4; o; o >>= 1) t += __shfl_xor_sync(0xffu, t, o);
        if (tid == 0) s_rs = rsqrtf(t * (1.f / CDIM) + 1e-5f);
    }
    __syncthreads();
    float rs = s_rs;
    float* orow = out + (size_t)row * CDIM;
#pragma unroll
    for (int i = 0; i < 4; i++) {
        int c = tid + i * 256;
        orow[c] = (v[i] - mu) * rs * gam[c] + bet[c];
    }
}

// tf32 HMMA GEMM: 128x128 tile, BK=32, 2-stage cp.async, 2 CTAs/SM.
// EPI: 0 store(+bias), 1 relu(+bias), 2 store+residual, 3 gated atomic scatter.
template <int EPI, bool GATHER>
__global__ __launch_bounds__(256, 2) void tgemm3_kernel(
    const float* __restrict__ A, const float* __restrict__ B, float* __restrict__ Cout,
    int M, int N, int K,
    const float* __restrict__ bias, const float* __restrict__ res,
    const int* __restrict__ sidx, const float* __restrict__ sgate,
    float* __restrict__ scat, const float* __restrict__ zrow,
    size_t sA, size_t sB, size_t sC, int sBias)
{
    extern __shared__ float dsm[];
    __shared__ const float* arow[128];

    const int z = blockIdx.z;
    if (!GATHER) A += (size_t)z * sA;
    B += (size_t)z * sB;
    if (Cout) Cout += (size_t)z * sC;
    if (bias) bias += (size_t)z * sBias;

    const int tid = threadIdx.x;
    const int lane = tid & 31, wid = tid >> 5;
    const int wr = wid >> 2, wc = wid & 3;      // warp tile 64(M) x 32(N)
    const int tg = lane >> 2, tq = lane & 3;

    if (tid < 128) {
        const float* p;
        if (GATHER) {
            int idx = sidx[z * M + blockIdx.y * 128 + tid];
            p = (idx >= 0) ? (A + (size_t)idx * K) : zrow;
        } else p = A + (size_t)(blockIdx.y * 128 + tid) * K;
        arow[tid] = p;
    }
    __syncthreads();

    const uint32_t sbase = (uint32_t)__cvta_generic_to_shared(dsm);
    const float* Bbase = B + blockIdx.x * 128;

#define ISSUE3(st, k0)                                                         \
    do {                                                                       \
        _Pragma("unroll")                                                      \
        for (int i_ = 0; i_ < 4; i_++) {                                       \
            int c_ = tid + i_ * 256;                                           \
            int row_ = c_ >> 3, kq_ = (c_ & 7) << 2;                           \
            uint32_t d_ = sbase + (uint32_t)(((st) * A3_STAGE + row_ * A3_STRIDE + kq_) * 4); \
            asm volatile("cp.async.cg.shared.global [%0], [%1], 16;"           \
                         :: "r"(d_), "l"(arow[row_] + (k0) + kq_));            \
        }                                                                      \
        _Pragma("unroll")                                                      \
        for (int i_ = 0; i_ < 4; i_++) {                                       \
            int c_ = tid + i_ * 256;                                           \
            int row_ = c_ >> 5, col_ = (c_ & 31) << 2;                         \
            uint32_t d_ = sbase + (uint32_t)((B3_OFF + (st) * B3_STAGE + row_ * B3_STRIDE + col_) * 4); \
            asm volatile("cp.async.cg.shared.global [%0], [%1], 16;"           \
                         :: "r"(d_), "l"(Bbase + (size_t)((k0) + row_) * N + col_)); \
        }                                                                      \
    } while (0)

    float acc[4][4][4];
#pragma unroll
    for (int i = 0; i < 4; i++)
#pragma unroll
        for (int j = 0; j < 4; j++)
#pragma unroll
            for (int q = 0; q < 4; q++) acc[i][j][q] = 0.f;

    const int KT = K >> 5;
    ISSUE3(0, 0);
    asm volatile("cp.async.commit_group;");
    ISSUE3(1, 32);
    asm volatile("cp.async.commit_group;");

    for (int it = 0; it < KT; it++) {
        asm volatile("cp.async.wait_group 1;");
        __syncthreads();
        const int st = it & 1;
        const float* As = dsm + st * A3_STAGE;
        const float* Bs = dsm + B3_OFF + st * B3_STAGE;
#pragma unroll
        for (int kk = 0; kk < 32; kk += 8) {
            uint32_t af[4][4], bf[4][2];
#pragma unroll
            for (int mi = 0; mi < 4; mi++) {
                int m0 = wr * 64 + mi * 16 + tg;
                af[mi][0] = __float_as_uint(As[m0 * A3_STRIDE + kk + tq]);
                af[mi][1] = __float_as_uint(As[(m0 + 8) * A3_STRIDE + kk + tq]);
                af[mi][2] = __float_as_uint(As[m0 * A3_STRIDE + kk + tq + 4]);
                af[mi][3] = __float_as_uint(As[(m0 + 8) * A3_STRIDE + kk + tq + 4]);
            }
#pragma unroll
            for (int ni = 0; ni < 4; ni++) {
                int n0 = wc * 32 + ni * 8 + tg;
                bf[ni][0] = __float_as_uint(Bs[(kk + tq) * B3_STRIDE + n0]);
                bf[ni][1] = __float_as_uint(Bs[(kk + tq + 4) * B3_STRIDE + n0]);
            }
#pragma unroll
            for (int mi = 0; mi < 4; mi++)
#pragma unroll
                for (int ni = 0; ni < 4; ni++)
                    mma_tf32(acc[mi][ni], af[mi], bf[ni]);
        }
        __syncthreads();                 // compute done before refilling this buffer
        if (it + 2 < KT) ISSUE3(st, (it + 2) * 32);
        asm volatile("cp.async.commit_group;");
    }
#undef ISSUE3

#pragma unroll
    for (int mi = 0; mi < 4; mi++) {
        int r0 = blockIdx.y * 128 + wr * 64 + mi * 16 + tg;
        int r1 = r0 + 8;
#pragma unroll
        for (int ni = 0; ni < 4; ni++) {
            int cc = blockIdx.x * 128 + wc * 32 + ni * 8 + tq * 2;
            float v00 = acc[mi][ni][0], v01 = acc[mi][ni][1];
            float v10 = acc[mi][ni][2], v11 = acc[mi][ni][3];
            if (bias) {
                float b0v = bias[cc], b1v = bias[cc + 1];
                v00 += b0v; v01 += b1v; v10 += b0v; v11 += b1v;
            }
            if (EPI == 1) {
                v00 = fmaxf(v00, 0.f); v01 = fmaxf(v01, 0.f);
                v10 = fmaxf(v10, 0.f); v11 = fmaxf(v11, 0.f);
            }
            if (EPI == 2) {
                float2 e0 = *(const float2*)&res[(size_t)r0 * N + cc];
                float2 e1 = *(const float2*)&res[(size_t)r1 * N + cc];
                v00 += e0.x; v01 += e0.y; v10 += e1.x; v11 += e1.y;
            }
            if (EPI == 3) {
                int gs0 = z * M + r0, gs1 = z * M + r1;
                int i0 = sidx[gs0], i1 = sidx[gs1];
                if (i0 >= 0) {
                    float g = sgate[gs0];
                    atomicAdd(&scat[(size_t)i0 * N + cc],     g * v00);
                    atomicAdd(&scat[(size_t)i0 * N + cc + 1], g * v01);
                }
                if (i1 >= 0) {
                    float g = sgate[gs1];
                    atomicAdd(&scat[(size_t)i1 * N + cc],     g * v10);
                    atomicAdd(&scat[(size_t)i1 * N + cc + 1], g * v11);
                }
            } else {
                *(float2*)&Cout[(size_t)r0 * N + cc] = make_float2(v00, v01);
                *(float2*)&Cout[(size_t)r1 * N + cc] = make_float2(v10, v11);
            }
        }
    }
}

__global__ __launch_bounds__(256) void attn_tc_kernel(const float* __restrict__ qkv,
                                                      float* __restrict__ aout) {
    __shared__ float Ks[64][72];
    __shared__ float Vs[64][72];
    const int bh = blockIdx.y, b = bh >> 4, h = bh & 15;
    const int tid = threadIdx.x, lane = tid & 31, w = tid >> 5;
    const int tg = lane >> 2, tq = lane & 3;
    const int q0 = blockIdx.x * 128 + w * 16;
    const float* qbase = qkv + (size_t)b * TSEQ * 3072 + h * 64;

    uint32_t qa[8][4];
    {
        const float* qr0 = qbase + (size_t)(q0 + tg) * 3072;
        const float* qr1 = qbase + (size_t)(q0 + tg + 8) * 3072;
#pragma unroll
        for (int kk = 0; kk < 8; kk++) {
            qa[kk][0] = __float_as_uint(ftf(qr0[kk * 8 + tq]     * 0.125f));
            qa[kk][1] = __float_as_uint(ftf(qr1[kk * 8 + tq]     * 0.125f));
            qa[kk][2] = __float_as_uint(ftf(qr0[kk * 8 + tq + 4] * 0.125f));
            qa[kk][3] = __float_as_uint(ftf(qr1[kk * 8 + tq + 4] * 0.125f));
        }
    }
    float oacc[8][4];
#pragma unroll
    for (int dt = 0; dt < 8; dt++)
#pragma unroll
        for (int i = 0; i < 4; i++) oacc[dt][i] = 0.f;
    float m0 = -1e30f, m1 = -1e30f, l0 = 0.f, l1 = 0.f;
    const float* kbase = qbase + 1024;
    const float* vbase = qbase + 2048;
    const int slo = (tg << 2) + (tq >> 1), shi = slo + 2;

    for (int s0 = 0; s0 < TSEQ; s0 += 64) {
        __syncthreads();
        for (int i = tid; i < 64 * 16; i += 256) {
            int j = i >> 4, dv = (i & 15) << 2;
            float4 kv = *(const float4*)(kbase + (size_t)(s0 + j) * 3072 + dv);
            float4 vv = *(const float4*)(vbase + (size_t)(s0 + j) * 3072 + dv);
            Ks[j][dv] = ftf(kv.x); Ks[j][dv + 1] = ftf(kv.y);
            Ks[j][dv + 2] = ftf(kv.z); Ks[j][dv + 3] = ftf(kv.w);
            Vs[j][dv] = ftf(vv.x); Vs[j][dv + 1] = ftf(vv.y);
            Vs[j][dv + 2] = ftf(vv.z); Vs[j][dv + 3] = ftf(vv.w);
        }
        __syncthreads();
        float s[8][4];
#pragma unroll
        for (int nt = 0; nt < 8; nt++) {
            s[nt][0] = s[nt][1] = s[nt][2] = s[nt][3] = 0.f;
#pragma unroll
            for (int kk = 0; kk < 8; kk++) {
                uint32_t bb[2] = {__float_as_uint(Ks[nt * 8 + tg][kk * 8 + tq]),
                                  __float_as_uint(Ks[nt * 8 + tg][kk * 8 + tq + 4])};
                mma_tf32(s[nt], qa[kk], bb);
            }
        }
        float rm0 = -1e30f, rm1 = -1e30f;
#pragma unroll
        for (int nt = 0; nt < 8; nt++) {
            rm0 = fmaxf(rm0, fmaxf(s[nt][0], s[nt][1]));
            rm1 = fmaxf(rm1, fmaxf(s[nt][2], s[nt][3]));
        }
        rm0 = fmaxf(rm0, __shfl_xor_sync(~0u, rm0, 1));
        rm0 = fmaxf(rm0, __shfl_xor_sync(~0u, rm0, 2));
        rm1 = fmaxf(rm1, __shfl_xor_sync(~0u, rm1, 1));
        rm1 = fmaxf(rm1, __shfl_xor_sync(~0u, rm1, 2));
        float mn0 = fmaxf(m0, rm0), mn1 = fmaxf(m1, rm1);
        float sc0 = __expf(m0 - mn0), sc1 = __expf(m1 - mn1);
        m0 = mn0; m1 = mn1;
        float rs0 = 0.f, rs1 = 0.f;
#pragma unroll
        for (int nt = 0; nt < 8; nt++) {
            s[nt][0] = __expf(s[nt][0] - mn0); s[nt][1] = __expf(s[nt][1] - mn0);
            s[nt][2] = __expf(s[nt][2] - mn1); s[nt][3] = __expf(s[nt][3] - mn1);
            rs0 += s[nt][0] + s[nt][1]; rs1 += s[nt][2] + s[nt][3];
        }
        rs0 += __shfl_xor_sync(~0u, rs0, 1); rs0 += __shfl_xor_sync(~0u, rs0, 2);
        rs1 += __shfl_xor_sync(~0u, rs1, 1); rs1 += __shfl_xor_sync(~0u, rs1, 2);
        l0 = l0 * sc0 + rs0; l1 = l1 * sc1 + rs1;
#pragma unroll
        for (int dt = 0; dt < 8; dt++) {
            oacc[dt][0] *= sc0; oacc[dt][1] *= sc0;
            oacc[dt][2] *= sc1; oacc[dt][3] *= sc1;
        }
#pragma unroll
        for (int kk = 0; kk < 8; kk++) {
            uint32_t pa[4]; float e, o;
            e = __shfl_sync(~0u, s[kk][0], slo); o = __shfl_sync(~0u, s[kk][1], slo);
            pa[0] = __float_as_uint((tq & 1) ? o : e);
            e = __shfl_sync(~0u, s[kk][2], slo); o = __shfl_sync(~0u, s[kk][3], slo);
            pa[1] = __float_as_uint((tq & 1) ? o : e);
            e = __shfl_sync(~0u, s[kk][0], shi); o = __shfl_sync(~0u, s[kk][1], shi);
            pa[2] = __float_as_uint((tq & 1) ? o : e);
            e = __shfl_sync(~0u, s[kk][2], shi); o = __shfl_sync(~0u, s[kk][3], shi);
            pa[3] = __float_as_uint((tq & 1) ? o : e);
#pragma unroll
            for (int dt = 0; dt < 8; dt++) {
                uint32_t bb[2] = {__float_as_uint(Vs[kk * 8 + tq][dt * 8 + tg]),
                                  __float_as_uint(Vs[kk * 8 + tq + 4][dt * 8 + tg])};
                mma_tf32(oacc[dt], pa, bb);
            }
        }
    }
    float inv0 = 1.f / l0, inv1 = 1.f / l1;
    float* ab = aout + (size_t)b * TSEQ * CDIM;
    int t0 = q0 + tg, t1 = t0 + 8;
    int c0 = h * 64 + (t0 >> 5), r0b = (t0 & 31) * 64;
    int c1 = h * 64 + (t1 >> 5), r1b = (t1 & 31) * 64;
#pragma unroll
    for (int dt = 0; dt < 8; dt++) {
        int dd = dt * 8 + tq * 2;
        ab[(size_t)(r0b + dd) * CDIM + c0]     = oacc[dt][0] * inv0;
        ab[(size_t)(r0b + dd + 1) * CDIM + c0] = oacc[dt][1] * inv0;
        ab[(size_t)(r1b + dd) * CDIM + c1]     = oacc[dt][2] * inv1;
        ab[(size_t)(r1b + dd + 1) * CDIM + c1] = oacc[dt][3] * inv1;
    }
}

__global__ __launch_bounds__(256) void route_kernel(const float* __restrict__ wr,
                                                    const float* __restrict__ br,
                                                    const float* __restrict__ wn,
                                                    const float* __restrict__ bn) {
    int warp = threadIdx.x >> 5, lane = threadIdx.x & 31;
    int n = blockIdx.x * 8 + warp;
    const float* hp = g_h2 + (size_t)n * CDIM;
    float pr[8], pn[8];
#pragma unroll
    for (int e = 0; e < 8; e++) { pr[e] = 0.f; pn[e] = 0.f; }
    for (int c = lane; c < CDIM; c += 32) {
        float hv = hp[c];
#pragma unroll
        for (int e = 0; e < 8; e++) {
            pr[e] += hv * wr[c * 8 + e];
            pn[e] += hv * wn[c * 8 + e];
        }
    }
#pragma unroll
    for (int e = 0; e < 8; e++)
        for (int o = 16; o; o >>= 1) {
            pr[e] += __shfl_xor_sync(~0u, pr[e], o);
            pn[e] += __shfl_xor_sync(~0u, pn[e], o);
        }
    if (lane == 0)
#pragma unroll
        for (int e = 0; e < 8; e++) {
            g_logits[n * 8 + e]  = pr[e] + br[e];
            g_nlogits[n * 8 + e] = pn[e] + bn[e];
        }
}

__global__ __launch_bounds__(256) void route_post_kernel(const float* __restrict__ noise) {
    __shared__ float red[8];
    int n = blockIdx.x * blockDim.x + threadIdx.x;
    float noisy[8], mx = -1e30f;
#pragma unroll
    for (int e = 0; e < 8; e++) {
        float nl = g_nlogits[n * 8 + e];
        float sp = log1pf(expf(-fabsf(nl))) + fmaxf(nl, 0.f);
        float v = g_logits[n * 8 + e] + noise[n * 8 + e] * sp;
        noisy[e] = v; mx = fmaxf(mx, v);
    }
    float s = 0.f, p[8];
#pragma unroll
    for (int e = 0; e < 8; e++) { p[e] = expf(noisy[e] - mx); s += p[e]; }
    float inv = 1.f / s, ent = 0.f;
#pragma unroll
    for (int e = 0; e < 8; e++) { float pe = p[e] * inv; ent -= pe * logf(pe + 1e-8f); }
    int i0 = 0;
#pragma unroll
    for (int e = 1; e < 8; e++) if (noisy[e] > noisy[i0]) i0 = e;
    int i1 = (i0 == 0) ? 1 : 0;
#pragma unroll
    for (int e = 0; e < 8; e++) if (e != i0 && noisy[e] > noisy[i1]) i1 = e;
    float dgl = expf(noisy[i1] - noisy[i0]);
    float g0 = 1.f / (1.f + dgl), g1 = dgl * g0;
    g_sel[n] = i0 | (i1 << 8);
    g_gate[2 * n] = g0; g_gate[2 * n + 1] = g1;
    float es = ent;
    for (int o = 16; o; o >>= 1) es += __shfl_xor_sync(~0u, es, o);
    int lane = threadIdx.x & 31, wid = threadIdx.x >> 5;
    if (lane == 0) red[wid] = es;
    __syncthreads();
    if (threadIdx.x < 8) {
        float t = red[threadIdx.x];
        for (int o = 4; o; o >>= 1) t += __shfl_xor_sync(0xffu, t, o);
        if (threadIdx.x == 0) atomicAdd(&g_ent, t);
    }
}

__global__ void assign_kernel() {
    int lane = threadIdx.x;
    int cnt[8];
#pragma unroll
    for (int e = 0; e < 8; e++) cnt[e] = 0;
    unsigned lt = (1u << lane) - 1u;
    for (int n0 = 0; n0 < NTOK; n0 += 32) {
        int n = n0 + lane;
        int sel = g_sel[n];
        int e0 = sel & 255, e1 = (sel >> 8) & 255;
        float g0 = g_gate[2 * n], g1 = g_gate[2 * n + 1];
#pragma unroll
        for (int e = 0; e < 8; e++) {
            bool mt = (e0 == e) || (e1 == e);
            unsigned mask = __ballot_sync(~0u, mt);
            if (mt) {
                int r = cnt[e] + __popc(mask & lt);
                if (r < CAP) {
                    g_slot_idx[e * CAP + r]  = n;
                    g_slot_gate[e * CAP + r] = (e0 == e) ? g0 : g1;
                }
            }
            cnt[e] += __popc(mask);
        }
    }
#pragma unroll
    for (int e = 0; e < 8; e++)
        for (int r = cnt[e] + lane; r < CAP; r += 32) {
            g_slot_idx[e * CAP + r]  = -1;
            g_slot_gate[e * CAP + r] = 0.f;
        }
}

__global__ void final_kernel(float* __restrict__ out, int out_size) {
    int i = blockIdx.x * blockDim.x + threadIdx.x;
    if (i < NTOK * CDIM) out[i] = g_x2[i] + g_upd[i];
    else if (i < out_size) out[i] = g_ent * (1.f / NTOK);
}

static float* symf(const void* s) { void* p = nullptr; cudaGetSymbolAddress(&p, s); return (float*)p; }
static int*   symi(const void* s) { void* p = nullptr; cudaGetSymbolAddress(&p, s); return (int*)p; }

extern "C" void kernel_launch(void* const* d_in, const int* in_sizes, int n_in,
                              void* d_out, int out_size) {
    const float* x       = (const float*)d_in[0];
    const float* noise   = (const float*)d_in[1];
    const float* gamma1  = (const float*)d_in[2];
    const float* beta1   = (const float*)d_in[3];
    const float* gamma2  = (const float*)d_in[4];
    const float* beta2   = (const float*)d_in[5];
    const float* w_qkv   = (const float*)d_in[6];
    const float* w_out   = (const float*)d_in[7];
    const float* w_route = (const float*)d_in[8];
    const float* b_route = (const float*)d_in[9];
    const float* w_noise = (const float*)d_in[10];
    const float* b_noise = (const float*)d_in[11];
    const float* w1      = (const float*)d_in[12];
    const float* b1      = (const float*)d_in[13];
    const float* w2      = (const float*)d_in[14];
    const float* b2      = (const float*)d_in[15];
    float* out = (float*)d_out;

    float* p_h1   = symf(g_h1);
    float* p_qkv  = symf(g_qkv);
    float* p_attn = symf(g_attn);
    float* p_x2   = symf(g_x2);
    float* p_h2   = symf(g_h2);
    float* p_hid  = symf(g_hid);
    float* p_upd  = symf(g_upd);
    float* p_zero = symf(g_zero);
    int*   p_sidx = symi(g_slot_idx);
    float* p_sg   = symf(g_slot_gate);

    static int smem_set = 0;
    if (!smem_set) {
        cudaFuncSetAttribute(tgemm3_kernel<0, false>, cudaFuncAttributeMaxDynamicSharedMemorySize, SMEM3_BYTES);
        cudaFuncSetAttribute(tgemm3_kernel<2, false>, cudaFuncAttributeMaxDynamicSharedMemorySize, SMEM3_BYTES);
        cudaFuncSetAttribute(tgemm3_kernel<1, true>,  cudaFuncAttributeMaxDynamicSharedMemorySize, SMEM3_BYTES);
        cudaFuncSetAttribute(tgemm3_kernel<3, false>, cudaFuncAttributeMaxDynamicSharedMemorySize, SMEM3_BYTES);
        smem_set = 1;
    }

    zero_kernel<<<NTOK * CDIM / 4 / 256, 256>>>();
    ln_kernel<<<NTOK, 256>>>(x, gamma1, beta1, p_h1);
    // qkv = h1 @ w_qkv
    tgemm3_kernel<0, false><<<dim3(3072 / 128, 4096 / 128, 1), 256, SMEM3_BYTES>>>(
        p_h1, w_qkv, p_qkv, 4096, 3072, 1024,
        nullptr, nullptr, nullptr, nullptr, nullptr, p_zero, 0, 0, 0, 0);
    attn_tc_kernel<<<dim3(TSEQ / 128, BSZ * 16), 256>>>(p_qkv, p_attn);
    // x2 = x + attn @ w_out
    tgemm3_kernel<2, false><<<dim3(1024 / 128, 4096 / 128, 1), 256, SMEM3_BYTES>>>(
        p_attn, w_out, p_x2, 4096, 1024, 1024,
        nullptr, x, nullptr, nullptr, nullptr, p_zero, 0, 0, 0, 0);
    ln_kernel<<<NTOK, 256>>>(p_x2, gamma2, beta2, p_h2);
    route_kernel<<<NTOK / 8, 256>>>(w_route, b_route, w_noise, b_noise);
    route_post_kernel<<<NTOK / 256, 256>>>(noise);
    assign_kernel<<<1, 32>>>();
    // hid = relu(h2[slot] @ w1 + b1), fused gather
    tgemm3_kernel<1, true><<<dim3(4096 / 128, 1024 / 128, NEXP), 256, SMEM3_BYTES>>>(
        p_h2, w1, p_hid, 1024, 4096, 1024,
        b1, nullptr, p_sidx, nullptr, nullptr, p_zero,
        0, (size_t)CDIM * DFF, (size_t)CAP * DFF, DFF);
    // yo = hid @ w2 + b2, gated atomic scatter
    tgemm3_kernel<3, false><<<dim3(1024 / 128, 1024 / 128, NEXP), 256, SMEM3_BYTES>>>(
        p_hid, w2, nullptr, 1024, 1024, 4096,
        b2, nullptr, p_sidx, p_sg, p_upd, p_zero,
        (size_t)CAP * DFF, (size_t)DFF * CDIM, 0, CDIM);
    final_kernel<<<(out_size + 255) / 256, 256>>>(out, out_size);
}

// round 10
// speedup vs baseline: 1.2934x; 1.2116x over previous
#include <cuda_runtime.h>
#include <cuda_fp16.h>
#include <math.h>
#include <stdint.h>

#define NTOK 4096
#define CDIM 1024
#define NEXP 8
#define DFF  4096
#define CAP  1024
#define TSEQ 2048
#define BSZ  2

// tgemm4 (fp16): 128x128 tile, BK=32, 3 stages
#define A4_STAGE_B 10240                 // 128 rows * 80 B (40 halves)
#define B4_STAGE_B 8704                  // 16 rows * 544 B (136 words)
#define B4_OFF_B   30720                 // 3 * A4_STAGE_B
#define SMEM4_BYTES (B4_OFF_B + 3 * B4_STAGE_B)   // 56832

__device__ __align__(16) __half g_h1h [NTOK * CDIM];
__device__ float g_qkv  [NTOK * 3 * CDIM];
__device__ __align__(16) __half g_attnh[NTOK * CDIM];
__device__ float g_x2   [NTOK * CDIM];
__device__ float g_h2   [NTOK * CDIM];
__device__ __align__(16) __half g_h2h [NTOK * CDIM];
__device__ float g_logits [NTOK * NEXP];
__device__ float g_nlogits[NTOK * NEXP];
__device__ int   g_sel  [NTOK];
__device__ float g_gate [NTOK * 2];
__device__ int   g_slot_idx [NEXP * CAP];
__device__ float g_slot_gate[NEXP * CAP];
__device__ __align__(16) __half g_zeroh[CDIM];
__device__ __align__(16) __half g_hidh [(size_t)NEXP * CAP * DFF];
__device__ float g_upd [NTOK * CDIM];
__device__ float g_ent;
__device__ __align__(16) __half2 g_wqkvh[512 * 3072];
__device__ __align__(16) __half2 g_wouth[512 * 1024];
__device__ __align__(16) __half2 g_w1h[(size_t)NEXP * 512 * DFF];
__device__ __align__(16) __half2 g_w2h[(size_t)NEXP * 2048 * CDIM];

__device__ __forceinline__ float ftf(float x) {
    float r; asm("cvt.rna.tf32.f32 %0, %1;" : "=f"(r) : "f"(x)); return r;
}
__device__ __forceinline__ void mma_tf32(float c[4], const uint32_t a[4], const uint32_t b[2]) {
    asm volatile("mma.sync.aligned.m16n8k8.row.col.f32.tf32.tf32.f32 "
        "{%0,%1,%2,%3},{%4,%5,%6,%7},{%8,%9},{%0,%1,%2,%3};"
        : "+f"(c[0]), "+f"(c[1]), "+f"(c[2]), "+f"(c[3])
        : "r"(a[0]), "r"(a[1]), "r"(a[2]), "r"(a[3]), "r"(b[0]), "r"(b[1]));
}
__device__ __forceinline__ void mma_f16(float c[4], const uint32_t a[4], const uint32_t b[2]) {
    asm volatile("mma.sync.aligned.m16n8k16.row.col.f32.f16.f16.f32 "
        "{%0,%1,%2,%3},{%4,%5,%6,%7},{%8,%9},{%0,%1,%2,%3};"
        : "+f"(c[0]), "+f"(c[1]), "+f"(c[2]), "+f"(c[3])
        : "r"(a[0]), "r"(a[1]), "r"(a[2]), "r"(a[3]), "r"(b[0]), "r"(b[1]));
}

__global__ void zero_kernel() {
    size_t i = (size_t)blockIdx.x * blockDim.x + threadIdx.x;
    ((float4*)g_upd)[i] = make_float4(0.f, 0.f, 0.f, 0.f);
    if (i < CDIM / 8) ((float4*)g_zeroh)[i] = make_float4(0.f, 0.f, 0.f, 0.f);
    if (i == 0) g_ent = 0.f;
}

// pack fp32 [K][N] -> half2 [K/2][N] with k-pair interleave
__global__ __launch_bounds__(256) void convw_kernel(const float* __restrict__ src,
                                                    __half2* __restrict__ dst,
                                                    int K2, int N) {
    size_t z = blockIdx.z;
    src += z * (size_t)K2 * 2 * N;
    dst += z * (size_t)K2 * N;
    size_t i = (size_t)blockIdx.x * 256 + threadIdx.x;
    int k2 = (int)(i / N), n = (int)(i % N);
    dst[i] = __floats2half2_rn(src[(size_t)(2 * k2) * N + n], src[(size_t)(2 * k2 + 1) * N + n]);
}

__global__ __launch_bounds__(256) void ln_kernel(const float* __restrict__ x,
                                                 const float* __restrict__ gam,
                                                 const float* __restrict__ bet,
                                                 float* __restrict__ out,
                                                 __half* __restrict__ outh) {
    __shared__ float red[8];
    __shared__ float s_mu, s_rs;
    int row = blockIdx.x, tid = threadIdx.x;
    const float* xr = x + (size_t)row * CDIM;
    float v[4]; float s = 0.f;
#pragma unroll
    for (int i = 0; i < 4; i++) { v[i] = xr[tid + i * 256]; s += v[i]; }
    for (int o = 16; o; o >>= 1) s += __shfl_xor_sync(~0u, s, o);
    if ((tid & 31) == 0) red[tid >> 5] = s;
    __syncthreads();
    if (tid < 8) {
        float t = red[tid];
        for (int o = 4; o; o >>= 1) t += __shfl_xor_sync(0xffu, t, o);
        if (tid == 0) s_mu = t * (1.f / CDIM);
    }
    __syncthreads();
    float mu = s_mu, s2 = 0.f;
#pragma unroll
    for (int i = 0; i < 4; i++) { float d = v[i] - mu; s2 += d * d; }
    for (int o = 16; o; o >>= 1) s2 += __shfl_xor_sync(~0u, s2, o);
    if ((tid & 31) == 0) red[tid >> 5] = s2;
    __syncthreads();
    if (tid < 8) {
        float t = red[tid];
        for (int o = 4; o; o >>= 1) t += __shfl_xor_sync(0xffu, t, o);
        if (tid == 0) s_rs = rsqrtf(t * (1.f / CDIM) + 1e-5f);
    }
    __syncthreads();
    float rs = s_rs;
#pragma unroll
    for (int i = 0; i < 4; i++) {
        int c = tid + i * 256;
        float val = (v[i] - mu) * rs * gam[c] + bet[c];
        if (out)  out[(size_t)row * CDIM + c] = val;
        if (outh) outh[(size_t)row * CDIM + c] = __float2half(val);
    }
}

// fp16 HMMA GEMM: 128x128 tile, BK=32, 3-stage cp.async, 2 CTAs/SM.
// A: half [M][K]; B: half2 packed [K/2][N]. EPI 0/1/2/3; OUTH: write half.
template <int EPI, bool GATHER, bool OUTH>
__global__ __launch_bounds__(256, 2) void tgemm4_kernel(
    const __half* __restrict__ A, const __half2* __restrict__ Bh, void* __restrict__ Cout,
    int M, int N, int K,
    const float* __restrict__ bias, const float* __restrict__ res,
    const int* __restrict__ sidx, const float* __restrict__ sgate,
    float* __restrict__ scat, const __half* __restrict__ zrow,
    size_t sA, size_t sB, size_t sC, int sBias)
{
    extern __shared__ float dsm[];
    __shared__ const __half* arow[128];

    const int z = blockIdx.z;
    const __half* Az = GATHER ? A : (A + (size_t)z * sA);
    const __half2* Bz = Bh + (size_t)z * sB;
    const float* bz = bias ? (bias + (size_t)z * sBias) : nullptr;

    const int tid = threadIdx.x;
    const int lane = tid & 31, wid = tid >> 5;
    const int wr = wid >> 2, wc = wid & 3;
    const int tg = lane >> 2, tq = lane & 3;

    if (tid < 128) {
        const __half* p;
        if (GATHER) {
            int idx = sidx[z * M + blockIdx.y * 128 + tid];
            p = (idx >= 0) ? (Az + (size_t)idx * K) : zrow;
        } else p = Az + (size_t)(blockIdx.y * 128 + tid) * K;
        arow[tid] = p;
    }
    __syncthreads();

    const uint32_t sbase = (uint32_t)__cvta_generic_to_shared(dsm);
    const int bxn = blockIdx.x * 128;

#define ISSUE4(st, k0)                                                         \
    do {                                                                       \
        _Pragma("unroll")                                                      \
        for (int j_ = 0; j_ < 2; j_++) {                                       \
            int c_ = tid + j_ * 256;                                           \
            int row_ = c_ >> 2, ch_ = c_ & 3;                                  \
            uint32_t d_ = sbase + (uint32_t)((st) * A4_STAGE_B + row_ * 80 + ch_ * 16); \
            asm volatile("cp.async.cg.shared.global [%0], [%1], 16;"           \
                         :: "r"(d_), "l"(arow[row_] + (k0) + ch_ * 8));        \
        }                                                                      \
        _Pragma("unroll")                                                      \
        for (int j_ = 0; j_ < 2; j_++) {                                       \
            int c_ = tid + j_ * 256;                                           \
            int k2_ = c_ >> 5, n4_ = c_ & 31;                                  \
            uint32_t d_ = sbase + (uint32_t)(B4_OFF_B + (st) * B4_STAGE_B + k2_ * 544 + n4_ * 16); \
            asm volatile("cp.async.cg.shared.global [%0], [%1], 16;"           \
                         :: "r"(d_), "l"(Bz + (size_t)((k0) / 2 + k2_) * N + bxn + n4_ * 4)); \
        }                                                                      \
    } while (0)

    float acc[4][4][4];
#pragma unroll
    for (int i = 0; i < 4; i++)
#pragma unroll
        for (int j = 0; j < 4; j++)
#pragma unroll
            for (int q = 0; q < 4; q++) acc[i][j][q] = 0.f;

    const int KT = K >> 5;
    ISSUE4(0, 0);
    asm volatile("cp.async.commit_group;");
    ISSUE4(1, 32);
    asm volatile("cp.async.commit_group;");

    for (int it = 0; it < KT; it++) {
        asm volatile("cp.async.wait_group 1;");
        __syncthreads();
        if (it + 2 < KT) ISSUE4((it + 2) % 3, (it + 2) * 32);
        asm volatile("cp.async.commit_group;");

        const int st = it % 3;
        const char* Asb = (const char*)dsm + st * A4_STAGE_B;
        const char* Bsb = (const char*)dsm + B4_OFF_B + st * B4_STAGE_B;
#pragma unroll
        for (int c = 0; c < 2; c++) {       // two k16 chunks
            uint32_t af[4][4], bf[4][2];
#pragma unroll
            for (int mi = 0; mi < 4; mi++) {
                int m0 = wr * 64 + mi * 16 + tg;
                const char* p0 = Asb + m0 * 80 + c * 32 + tq * 4;
                const char* p1 = Asb + (m0 + 8) * 80 + c * 32 + tq * 4;
                af[mi][0] = *(const uint32_t*)p0;
                af[mi][1] = *(const uint32_t*)p1;
                af[mi][2] = *(const uint32_t*)(p0 + 16);
                af[mi][3] = *(const uint32_t*)(p1 + 16);
            }
#pragma unroll
            for (int ni = 0; ni < 4; ni++) {
                int n0 = wc * 32 + ni * 8 + tg;
                const char* pb = Bsb + (c * 8 + tq) * 544 + n0 * 4;
                bf[ni][0] = *(const uint32_t*)pb;
                bf[ni][1] = *(const uint32_t*)(pb + 4 * 544);
            }
#pragma unroll
            for (int mi = 0; mi < 4; mi++)
#pragma unroll
                for (int ni = 0; ni < 4; ni++)
                    mma_f16(acc[mi][ni], af[mi], bf[ni]);
        }
    }
#undef ISSUE4

#pragma unroll
    for (int mi = 0; mi < 4; mi++) {
        int r0 = blockIdx.y * 128 + wr * 64 + mi * 16 + tg;
        int r1 = r0 + 8;
#pragma unroll
        for (int ni = 0; ni < 4; ni++) {
            int cc = blockIdx.x * 128 + wc * 32 + ni * 8 + tq * 2;
            float v00 = acc[mi][ni][0], v01 = acc[mi][ni][1];
            float v10 = acc[mi][ni][2], v11 = acc[mi][ni][3];
            if (bz) {
                float b0v = bz[cc], b1v = bz[cc + 1];
                v00 += b0v; v01 += b1v; v10 += b0v; v11 += b1v;
            }
            if (EPI == 1) {
                v00 = fmaxf(v00, 0.f); v01 = fmaxf(v01, 0.f);
                v10 = fmaxf(v10, 0.f); v11 = fmaxf(v11, 0.f);
            }
            if (EPI == 2) {
                float2 e0 = *(const float2*)&res[(size_t)r0 * N + cc];
                float2 e1 = *(const float2*)&res[(size_t)r1 * N + cc];
                v00 += e0.x; v01 += e0.y; v10 += e1.x; v11 += e1.y;
            }
            if (EPI == 3) {
                int gs0 = z * M + r0, gs1 = z * M + r1;
                int i0 = sidx[gs0], i1 = sidx[gs1];
                if (i0 >= 0) {
                    float g = sgate[gs0];
                    atomicAdd(&scat[(size_t)i0 * N + cc],     g * v00);
                    atomicAdd(&scat[(size_t)i0 * N + cc + 1], g * v01);
                }
                if (i1 >= 0) {
                    float g = sgate[gs1];
                    atomicAdd(&scat[(size_t)i1 * N + cc],     g * v10);
                    atomicAdd(&scat[(size_t)i1 * N + cc + 1], g * v11);
                }
            } else if (OUTH) {
                __half* Ch = (__half*)Cout + (size_t)z * sC;
                *(__half2*)&Ch[(size_t)r0 * N + cc] = __floats2half2_rn(v00, v01);
                *(__half2*)&Ch[(size_t)r1 * N + cc] = __floats2half2_rn(v10, v11);
            } else {
                float* Cf = (float*)Cout + (size_t)z * sC;
                *(float2*)&Cf[(size_t)r0 * N + cc] = make_float2(v00, v01);
                *(float2*)&Cf[(size_t)r1 * N + cc] = make_float2(v10, v11);
            }
        }
    }
}

__global__ __launch_bounds__(256) void attn_tc_kernel(const float* __restrict__ qkv,
                                                      __half* __restrict__ aout) {
    __shared__ float Ks[64][72];
    __shared__ float Vs[64][72];
    const int bh = blockIdx.y, b = bh >> 4, h = bh & 15;
    const int tid = threadIdx.x, lane = tid & 31, w = tid >> 5;
    const int tg = lane >> 2, tq = lane & 3;
    const int q0 = blockIdx.x * 128 + w * 16;
    const float* qbase = qkv + (size_t)b * TSEQ * 3072 + h * 64;

    uint32_t qa[8][4];
    {
        const float* qr0 = qbase + (size_t)(q0 + tg) * 3072;
        const float* qr1 = qbase + (size_t)(q0 + tg + 8) * 3072;
#pragma unroll
        for (int kk = 0; kk < 8; kk++) {
            qa[kk][0] = __float_as_uint(ftf(qr0[kk * 8 + tq]     * 0.125f));
            qa[kk][1] = __float_as_uint(ftf(qr1[kk * 8 + tq]     * 0.125f));
            qa[kk][2] = __float_as_uint(ftf(qr0[kk * 8 + tq + 4] * 0.125f));
            qa[kk][3] = __float_as_uint(ftf(qr1[kk * 8 + tq + 4] * 0.125f));
        }
    }
    float oacc[8][4];
#pragma unroll
    for (int dt = 0; dt < 8; dt++)
#pragma unroll
        for (int i = 0; i < 4; i++) oacc[dt][i] = 0.f;
    float m0 = -1e30f, m1 = -1e30f, l0 = 0.f, l1 = 0.f;
    const float* kbase = qbase + 1024;
    const float* vbase = qbase + 2048;
    const int slo = (tg << 2) + (tq >> 1), shi = slo + 2;

    for (int s0 = 0; s0 < TSEQ; s0 += 64) {
        __syncthreads();
        for (int i = tid; i < 64 * 16; i += 256) {
            int j = i >> 4, dv = (i & 15) << 2;
            float4 kv = *(const float4*)(kbase + (size_t)(s0 + j) * 3072 + dv);
            float4 vv = *(const float4*)(vbase + (size_t)(s0 + j) * 3072 + dv);
            Ks[j][dv] = ftf(kv.x); Ks[j][dv + 1] = ftf(kv.y);
            Ks[j][dv + 2] = ftf(kv.z); Ks[j][dv + 3] = ftf(kv.w);
            Vs[j][dv] = ftf(vv.x); Vs[j][dv + 1] = ftf(vv.y);
            Vs[j][dv + 2] = ftf(vv.z); Vs[j][dv + 3] = ftf(vv.w);
        }
        __syncthreads();
        float s[8][4];
#pragma unroll
        for (int nt = 0; nt < 8; nt++) {
            s[nt][0] = s[nt][1] = s[nt][2] = s[nt][3] = 0.f;
#pragma unroll
            for (int kk = 0; kk < 8; kk++) {
                uint32_t bb[2] = {__float_as_uint(Ks[nt * 8 + tg][kk * 8 + tq]),
                                  __float_as_uint(Ks[nt * 8 + tg][kk * 8 + tq + 4])};
                mma_tf32(s[nt], qa[kk], bb);
            }
        }
        float rm0 = -1e30f, rm1 = -1e30f;
#pragma unroll
        for (int nt = 0; nt < 8; nt++) {
            rm0 = fmaxf(rm0, fmaxf(s[nt][0], s[nt][1]));
            rm1 = fmaxf(rm1, fmaxf(s[nt][2], s[nt][3]));
        }
        rm0 = fmaxf(rm0, __shfl_xor_sync(~0u, rm0, 1));
        rm0 = fmaxf(rm0, __shfl_xor_sync(~0u, rm0, 2));
        rm1 = fmaxf(rm1, __shfl_xor_sync(~0u, rm1, 1));
        rm1 = fmaxf(rm1, __shfl_xor_sync(~0u, rm1, 2));
        float mn0 = fmaxf(m0, rm0), mn1 = fmaxf(m1, rm1);
        float sc0 = __expf(m0 - mn0), sc1 = __expf(m1 - mn1);
        m0 = mn0; m1 = mn1;
        float rs0 = 0.f, rs1 = 0.f;
#pragma unroll
        for (int nt = 0; nt < 8; nt++) {
            s[nt][0] = __expf(s[nt][0] - mn0); s[nt][1] = __expf(s[nt][1] - mn0);
            s[nt][2] = __expf(s[nt][2] - mn1); s[nt][3] = __expf(s[nt][3] - mn1);
            rs0 += s[nt][0] + s[nt][1]; rs1 += s[nt][2] + s[nt][3];
        }
        rs0 += __shfl_xor_sync(~0u, rs0, 1); rs0 += __shfl_xor_sync(~0u, rs0, 2);
        rs1 += __shfl_xor_sync(~0u, rs1, 1); rs1 += __shfl_xor_sync(~0u, rs1, 2);
        l0 = l0 * sc0 + rs0; l1 = l1 * sc1 + rs1;
#pragma unroll
        for (int dt = 0; dt < 8; dt++) {
            oacc[dt][0] *= sc0; oacc[dt][1] *= sc0;
            oacc[dt][2] *= sc1; oacc[dt][3] *= sc1;
        }
#pragma unroll
        for (int kk = 0; kk < 8; kk++) {
            uint32_t pa[4]; float e, o;
            e = __shfl_sync(~0u, s[kk][0], slo); o = __shfl_sync(~0u, s[kk][1], slo);
            pa[0] = __float_as_uint((tq & 1) ? o : e);
            e = __shfl_sync(~0u, s[kk][2], slo); o = __shfl_sync(~0u, s[kk][3], slo);
            pa[1] = __float_as_uint((tq & 1) ? o : e);
            e = __shfl_sync(~0u, s[kk][0], shi); o = __shfl_sync(~0u, s[kk][1], shi);
            pa[2] = __float_as_uint((tq & 1) ? o : e);
            e = __shfl_sync(~0u, s[kk][2], shi); o = __shfl_sync(~0u, s[kk][3], shi);
            pa[3] = __float_as_uint((tq & 1) ? o : e);
#pragma unroll
            for (int dt = 0; dt < 8; dt++) {
                uint32_t bb[2] = {__float_as_uint(Vs[kk * 8 + tq][dt * 8 + tg]),
                                  __float_as_uint(Vs[kk * 8 + tq + 4][dt * 8 + tg])};
                mma_tf32(oacc[dt], pa, bb);
            }
        }
    }
    float inv0 = 1.f / l0, inv1 = 1.f / l1;
    __half* ab = aout + (size_t)b * TSEQ * CDIM;
    int t0 = q0 + tg, t1 = t0 + 8;
    int c0 = h * 64 + (t0 >> 5), r0b = (t0 & 31) * 64;
    int c1 = h * 64 + (t1 >> 5), r1b = (t1 & 31) * 64;
#pragma unroll
    for (int dt = 0; dt < 8; dt++) {
        int dd = dt * 8 + tq * 2;
        ab[(size_t)(r0b + dd) * CDIM + c0]     = __float2half(oacc[dt][0] * inv0);
        ab[(size_t)(r0b + dd + 1) * CDIM + c0] = __float2half(oacc[dt][1] * inv0);
        ab[(size_t)(r1b + dd) * CDIM + c1]     = __float2half(oacc[dt][2] * inv1);
        ab[(size_t)(r1b + dd + 1) * CDIM + c1] = __float2half(oacc[dt][3] * inv1);
    }
}

__global__ __launch_bounds__(256) void route_kernel(const float* __restrict__ wr,
                                                    const float* __restrict__ br,
                                                    const float* __restrict__ wn,
                                                    const float* __restrict__ bn) {
    int warp = threadIdx.x >> 5, lane = threadIdx.x & 31;
    int n = blockIdx.x * 8 + warp;
    const float* hp = g_h2 + (size_t)n * CDIM;
    float pr[8], pn[8];
#pragma unroll
    for (int e = 0; e < 8; e++) { pr[e] = 0.f; pn[e] = 0.f; }
    for (int c = lane; c < CDIM; c += 32) {
        float hv = hp[c];
#pragma unroll
        for (int e = 0; e < 8; e++) {
            pr[e] += hv * wr[c * 8 + e];
            pn[e] += hv * wn[c * 8 + e];
        }
    }
#pragma unroll
    for (int e = 0; e < 8; e++)
        for (int o = 16; o; o >>= 1) {
            pr[e] += __shfl_xor_sync(~0u, pr[e], o);
            pn[e] += __shfl_xor_sync(~0u, pn[e], o);
        }
    if (lane == 0)
#pragma unroll
        for (int e = 0; e < 8; e++) {
            g_logits[n * 8 + e]  = pr[e] + br[e];
            g_nlogits[n * 8 + e] = pn[e] + bn[e];
        }
}

__global__ __launch_bounds__(256) void route_post_kernel(const float* __restrict__ noise) {
    __shared__ float red[8];
    int n = blockIdx.x * blockDim.x + threadIdx.x;
    float noisy[8], mx = -1e30f;
#pragma unroll
    for (int e = 0; e < 8; e++) {
        float nl = g_nlogits[n * 8 + e];
        float sp = log1pf(expf(-fabsf(nl))) + fmaxf(nl, 0.f);
        float v = g_logits[n * 8 + e] + noise[n * 8 + e] * sp;
        noisy[e] = v; mx = fmaxf(mx, v);
    }
    float s = 0.f, p[8];
#pragma unroll
    for (int e = 0; e < 8; e++) { p[e] = expf(noisy[e] - mx); s += p[e]; }
    float inv = 1.f / s, ent = 0.f;
#pragma unroll
    for (int e = 0; e < 8; e++) { float pe = p[e] * inv; ent -= pe * logf(pe + 1e-8f); }
    int i0 = 0;
#pragma unroll
    for (int e = 1; e < 8; e++) if (noisy[e] > noisy[i0]) i0 = e;
    int i1 = (i0 == 0) ? 1 : 0;
#pragma unroll
    for (int e = 0; e < 8; e++) if (e != i0 && noisy[e] > noisy[i1]) i1 = e;
    float dgl = expf(noisy[i1] - noisy[i0]);
    float g0 = 1.f / (1.f + dgl), g1 = dgl * g0;
    g_sel[n] = i0 | (i1 << 8);
    g_gate[2 * n] = g0; g_gate[2 * n + 1] = g1;
    float es = ent;
    for (int o = 16; o; o >>= 1) es += __shfl_xor_sync(~0u, es, o);
    int lane = threadIdx.x & 31, wid = threadIdx.x >> 5;
    if (lane == 0) red[wid] = es;
    __syncthreads();
    if (threadIdx.x < 8) {
        float t = red[threadIdx.x];
        for (int o = 4; o; o >>= 1) t += __shfl_xor_sync(0xffu, t, o);
        if (threadIdx.x == 0) atomicAdd(&g_ent, t);
    }
}

__global__ void assign_kernel() {
    int lane = threadIdx.x;
    int cnt[8];
#pragma unroll
    for (int e = 0; e < 8; e++) cnt[e] = 0;
    unsigned lt = (1u << lane) - 1u;
    for (int n0 = 0; n0 < NTOK; n0 += 32) {
        int n = n0 + lane;
        int sel = g_sel[n];
        int e0 = sel & 255, e1 = (sel >> 8) & 255;
        float g0 = g_gate[2 * n], g1 = g_gate[2 * n + 1];
#pragma unroll
        for (int e = 0; e < 8; e++) {
            bool mt = (e0 == e) || (e1 == e);
            unsigned mask = __ballot_sync(~0u, mt);
            if (mt) {
                int r = cnt[e] + __popc(mask & lt);
                if (r < CAP) {
                    g_slot_idx[e * CAP + r]  = n;
                    g_slot_gate[e * CAP + r] = (e0 == e) ? g0 : g1;
                }
            }
            cnt[e] += __popc(mask);
        }
    }
#pragma unroll
    for (int e = 0; e < 8; e++)
        for (int r = cnt[e] + lane; r < CAP; r += 32) {
            g_slot_idx[e * CAP + r]  = -1;
            g_slot_gate[e * CAP + r] = 0.f;
        }
}

__global__ void final_kernel(float* __restrict__ out, int out_size) {
    int i = blockIdx.x * blockDim.x + threadIdx.x;
    if (i < NTOK * CDIM) out[i] = g_x2[i] + g_upd[i];
    else if (i < out_size) out[i] = g_ent * (1.f / NTOK);
}

static void* symp(const void* s) { void* p = nullptr; cudaGetSymbolAddress(&p, s); return p; }

extern "C" void kernel_launch(void* const* d_in, const int* in_sizes, int n_in,
                              void* d_out, int out_size) {
    const float* x       = (const float*)d_in[0];
    const float* noise   = (const float*)d_in[1];
    const float* gamma1  = (const float*)d_in[2];
    const float* beta1   = (const float*)d_in[3];
    const float* gamma2  = (const float*)d_in[4];
    const float* beta2   = (const float*)d_in[5];
    const float* w_qkv   = (const float*)d_in[6];
    const float* w_out   = (const float*)d_in[7];
    const float* w_route = (const float*)d_in[8];
    const float* b_route = (const float*)d_in[9];
    const float* w_noise = (const float*)d_in[10];
    const float* b_noise = (const float*)d_in[11];
    const float* w1      = (const float*)d_in[12];
    const float* b1      = (const float*)d_in[13];
    const float* w2      = (const float*)d_in[14];
    const float* b2      = (const float*)d_in[15];
    float* out = (float*)d_out;

    __half*  p_h1h   = (__half*)symp(g_h1h);
    float*   p_qkv   = (float*)symp(g_qkv);
    __half*  p_attnh = (__half*)symp(g_attnh);
    float*   p_x2    = (float*)symp(g_x2);
    float*   p_h2    = (float*)symp(g_h2);
    __half*  p_h2h   = (__half*)symp(g_h2h);
    __half*  p_hidh  = (__half*)symp(g_hidh);
    float*   p_upd   = (float*)symp(g_upd);
    __half*  p_zeroh = (__half*)symp(g_zeroh);
    __half2* p_wqkvh = (__half2*)symp(g_wqkvh);
    __half2* p_wouth = (__half2*)symp(g_wouth);
    __half2* p_w1h   = (__half2*)symp(g_w1h);
    __half2* p_w2h   = (__half2*)symp(g_w2h);
    int*     p_sidx  = (int*)symp(g_slot_idx);
    float*   p_sg    = (float*)symp(g_slot_gate);

    static int smem_set = 0;
    if (!smem_set) {
        cudaFuncSetAttribute(tgemm4_kernel<0, false, false>, cudaFuncAttributeMaxDynamicSharedMemorySize, SMEM4_BYTES);
        cudaFuncSetAttribute(tgemm4_kernel<2, false, false>, cudaFuncAttributeMaxDynamicSharedMemorySize, SMEM4_BYTES);
        cudaFuncSetAttribute(tgemm4_kernel<1, true,  true >, cudaFuncAttributeMaxDynamicSharedMemorySize, SMEM4_BYTES);
        cudaFuncSetAttribute(tgemm4_kernel<3, false, false>, cudaFuncAttributeMaxDynamicSharedMemorySize, SMEM4_BYTES);
        smem_set = 1;
    }

    zero_kernel<<<NTOK * CDIM / 4 / 256, 256>>>();
    // weight packs (fp32 -> k-interleaved half2)
    convw_kernel<<<dim3(512 * 3072 / 256, 1, 1), 256>>>(w_qkv, p_wqkvh, 512, 3072);
    convw_kernel<<<dim3(512 * 1024 / 256, 1, 1), 256>>>(w_out, p_wouth, 512, 1024);
    convw_kernel<<<dim3(512 * DFF / 256, 1, NEXP), 256>>>(w1, p_w1h, 512, DFF);
    convw_kernel<<<dim3(2048 * CDIM / 256, 1, NEXP), 256>>>(w2, p_w2h, 2048, CDIM);

    ln_kernel<<<NTOK, 256>>>(x, gamma1, beta1, nullptr, p_h1h);
    // qkv = h1 @ w_qkv (fp32 out for attention)
    tgemm4_kernel<0, false, false><<<dim3(3072 / 128, 4096 / 128, 1), 256, SMEM4_BYTES>>>(
        p_h1h, p_wqkvh, p_qkv, 4096, 3072, 1024,
        nullptr, nullptr, nullptr, nullptr, nullptr, p_zeroh, 0, 0, 0, 0);
    attn_tc_kernel<<<dim3(TSEQ / 128, BSZ * 16), 256>>>(p_qkv, p_attnh);
    // x2 = x + attn @ w_out
    tgemm4_kernel<2, false, false><<<dim3(1024 / 128, 4096 / 128, 1), 256, SMEM4_BYTES>>>(
        p_attnh, p_wouth, p_x2, 4096, 1024, 1024,
        nullptr, x, nullptr, nullptr, nullptr, p_zeroh, 0, 0, 0, 0);
    ln_kernel<<<NTOK, 256>>>(p_x2, gamma2, beta2, p_h2, p_h2h);
    route_kernel<<<NTOK / 8, 256>>>(w_route, b_route, w_noise, b_noise);
    route_post_kernel<<<NTOK / 256, 256>>>(noise);
    assign_kernel<<<1, 32>>>();
    // hid = relu(h2[slot] @ w1 + b1), fused gather, half output
    tgemm4_kernel<1, true, true><<<dim3(DFF / 128, 1024 / 128, NEXP), 256, SMEM4_BYTES>>>(
        p_h2h, p_w1h, p_hidh, 1024, DFF, 1024,
        b1, nullptr, p_sidx, nullptr, nullptr, p_zeroh,
        0, (size_t)512 * DFF, (size_t)CAP * DFF, DFF);
    // yo = hid @ w2 + b2, gated atomic scatter
    tgemm4_kernel<3, false, false><<<dim3(1024 / 128, 1024 / 128, NEXP), 256, SMEM4_BYTES>>>(
        p_hidh, p_w2h, nullptr, 1024, 1024, 4096,
        b2, nullptr, p_sidx, p_sg, p_upd, p_zeroh,
        (size_t)CAP * DFF, (size_t)2048 * CDIM, 0, CDIM);
    final_kernel<<<(out_size + 255) / 256, 256>>>(out, out_size);
}

// round 11
// speedup vs baseline: 1.5279x; 1.1813x over previous
#include <cuda_runtime.h>
#include <cuda_fp16.h>
#include <math.h>
#include <stdint.h>

#define NTOK 4096
#define CDIM 1024
#define NEXP 8
#define DFF  4096
#define CAP  1024
#define TSEQ 2048
#define BSZ  2

// tgemm4 (fp16): 128x128 tile, BK=32, 3 stages
#define A4_STAGE_B 10240
#define B4_STAGE_B 8704
#define B4_OFF_B   30720
#define SMEM4_BYTES (B4_OFF_B + 3 * B4_STAGE_B)

__device__ __align__(16) __half g_h1h [NTOK * CDIM];
__device__ float g_qkv  [NTOK * 3 * CDIM];
__device__ __align__(16) __half g_attnh[NTOK * CDIM];
__device__ float g_x2   [NTOK * CDIM];
__device__ float g_h2   [NTOK * CDIM];
__device__ __align__(16) __half g_h2h [NTOK * CDIM];
__device__ float g_logits [NTOK * NEXP];
__device__ float g_nlogits[NTOK * NEXP];
__device__ int   g_sel  [NTOK];
__device__ float g_gate [NTOK * 2];
__device__ int   g_slot_idx [NEXP * CAP];
__device__ float g_slot_gate[NEXP * CAP];
__device__ __align__(16) __half g_zeroh[CDIM];
__device__ __align__(16) __half g_hidh [(size_t)NEXP * CAP * DFF];
__device__ float g_upd [NTOK * CDIM];
__device__ float g_ent;
__device__ __align__(16) __half2 g_wqkvh[512 * 3072];
__device__ __align__(16) __half2 g_wouth[512 * 1024];
__device__ __align__(16) __half2 g_w1h[(size_t)NEXP * 512 * DFF];
__device__ __align__(16) __half2 g_w2h[(size_t)NEXP * 2048 * CDIM];

__device__ __forceinline__ void mma_f16(float c[4], const uint32_t a[4], const uint32_t b[2]) {
    asm volatile("mma.sync.aligned.m16n8k16.row.col.f32.f16.f16.f32 "
        "{%0,%1,%2,%3},{%4,%5,%6,%7},{%8,%9},{%0,%1,%2,%3};"
        : "+f"(c[0]), "+f"(c[1]), "+f"(c[2]), "+f"(c[3])
        : "r"(a[0]), "r"(a[1]), "r"(a[2]), "r"(a[3]), "r"(b[0]), "r"(b[1]));
}
__device__ __forceinline__ uint32_t packh2(float a, float b) {
    __half2 h = __floats2half2_rn(a, b);
    return *(uint32_t*)&h;
}

__global__ void zero_kernel() {
    size_t i = (size_t)blockIdx.x * blockDim.x + threadIdx.x;
    ((float4*)g_upd)[i] = make_float4(0.f, 0.f, 0.f, 0.f);
    if (i < CDIM / 8) ((float4*)g_zeroh)[i] = make_float4(0.f, 0.f, 0.f, 0.f);
    if (i == 0) g_ent = 0.f;
}

// pack fp32 [K][N] -> half2 [K/2][N], vectorized 4 columns/thread
__global__ __launch_bounds__(256) void convw_kernel(const float* __restrict__ src,
                                                    __half2* __restrict__ dst,
                                                    int K2, int N) {
    size_t z = blockIdx.z;
    src += z * (size_t)K2 * 2 * N;
    dst += z * (size_t)K2 * N;
    size_t i4 = (size_t)blockIdx.x * 256 + threadIdx.x;   // group of 4 columns
    int n4 = N >> 2;
    int k2 = (int)(i4 / n4), n = (int)(i4 % n4) << 2;
    float4 r0 = *(const float4*)&src[(size_t)(2 * k2) * N + n];
    float4 r1 = *(const float4*)&src[(size_t)(2 * k2 + 1) * N + n];
    uint4 o;
    o.x = packh2(r0.x, r1.x); o.y = packh2(r0.y, r1.y);
    o.z = packh2(r0.z, r1.z); o.w = packh2(r0.w, r1.w);
    *(uint4*)&dst[(size_t)k2 * N + n] = o;
}

__global__ __launch_bounds__(256) void ln_kernel(const float* __restrict__ x,
                                                 const float* __restrict__ gam,
                                                 const float* __restrict__ bet,
                                                 float* __restrict__ out,
                                                 __half* __restrict__ outh) {
    __shared__ float red[8];
    __shared__ float s_mu, s_rs;
    int row = blockIdx.x, tid = threadIdx.x;
    const float* xr = x + (size_t)row * CDIM;
    float v[4]; float s = 0.f;
#pragma unroll
    for (int i = 0; i < 4; i++) { v[i] = xr[tid + i * 256]; s += v[i]; }
    for (int o = 16; o; o >>= 1) s += __shfl_xor_sync(~0u, s, o);
    if ((tid & 31) == 0) red[tid >> 5] = s;
    __syncthreads();
    if (tid < 8) {
        float t = red[tid];
        for (int o = 4; o; o >>= 1) t += __shfl_xor_sync(0xffu, t, o);
        if (tid == 0) s_mu = t * (1.f / CDIM);
    }
    __syncthreads();
    float mu = s_mu, s2 = 0.f;
#pragma unroll
    for (int i = 0; i < 4; i++) { float d = v[i] - mu; s2 += d * d; }
    for (int o = 16; o; o >>= 1) s2 += __shfl_xor_sync(~0u, s2, o);
    if ((tid & 31) == 0) red[tid >> 5] = s2;
    __syncthreads();
    if (tid < 8) {
        float t = red[tid];
        for (int o = 4; o; o >>= 1) t += __shfl_xor_sync(0xffu, t, o);
        if (tid == 0) s_rs = rsqrtf(t * (1.f / CDIM) + 1e-5f);
    }
    __syncthreads();
    float rs = s_rs;
#pragma unroll
    for (int i = 0; i < 4; i++) {
        int c = tid + i * 256;
        float val = (v[i] - mu) * rs * gam[c] + bet[c];
        if (out)  out[(size_t)row * CDIM + c] = val;
        if (outh) outh[(size_t)row * CDIM + c] = __float2half(val);
    }
}

// fp16 HMMA GEMM (unchanged from R10)
template <int EPI, bool GATHER, bool OUTH>
__global__ __launch_bounds__(256, 2) void tgemm4_kernel(
    const __half* __restrict__ A, const __half2* __restrict__ Bh, void* __restrict__ Cout,
    int M, int N, int K,
    const float* __restrict__ bias, const float* __restrict__ res,
    const int* __restrict__ sidx, const float* __restrict__ sgate,
    float* __restrict__ scat, const __half* __restrict__ zrow,
    size_t sA, size_t sB, size_t sC, int sBias)
{
    extern __shared__ float dsm[];
    __shared__ const __half* arow[128];

    const int z = blockIdx.z;
    const __half* Az = GATHER ? A : (A + (size_t)z * sA);
    const __half2* Bz = Bh + (size_t)z * sB;
    const float* bz = bias ? (bias + (size_t)z * sBias) : nullptr;

    const int tid = threadIdx.x;
    const int lane = tid & 31, wid = tid >> 5;
    const int wr = wid >> 2, wc = wid & 3;
    const int tg = lane >> 2, tq = lane & 3;

    if (tid < 128) {
        const __half* p;
        if (GATHER) {
            int idx = sidx[z * M + blockIdx.y * 128 + tid];
            p = (idx >= 0) ? (Az + (size_t)idx * K) : zrow;
        } else p = Az + (size_t)(blockIdx.y * 128 + tid) * K;
        arow[tid] = p;
    }
    __syncthreads();

    const uint32_t sbase = (uint32_t)__cvta_generic_to_shared(dsm);
    const int bxn = blockIdx.x * 128;

#define ISSUE4(st, k0)                                                         \
    do {                                                                       \
        _Pragma("unroll")                                                      \
        for (int j_ = 0; j_ < 2; j_++) {                                       \
            int c_ = tid + j_ * 256;                                           \
            int row_ = c_ >> 2, ch_ = c_ & 3;                                  \
            uint32_t d_ = sbase + (uint32_t)((st) * A4_STAGE_B + row_ * 80 + ch_ * 16); \
            asm volatile("cp.async.cg.shared.global [%0], [%1], 16;"           \
                         :: "r"(d_), "l"(arow[row_] + (k0) + ch_ * 8));        \
        }                                                                      \
        _Pragma("unroll")                                                      \
        for (int j_ = 0; j_ < 2; j_++) {                                       \
            int c_ = tid + j_ * 256;                                           \
            int k2_ = c_ >> 5, n4_ = c_ & 31;                                  \
            uint32_t d_ = sbase + (uint32_t)(B4_OFF_B + (st) * B4_STAGE_B + k2_ * 544 + n4_ * 16); \
            asm volatile("cp.async.cg.shared.global [%0], [%1], 16;"           \
                         :: "r"(d_), "l"(Bz + (size_t)((k0) / 2 + k2_) * N + bxn + n4_ * 4)); \
        }                                                                      \
    } while (0)

    float acc[4][4][4];
#pragma unroll
    for (int i = 0; i < 4; i++)
#pragma unroll
        for (int j = 0; j < 4; j++)
#pragma unroll
            for (int q = 0; q < 4; q++) acc[i][j][q] = 0.f;

    const int KT = K >> 5;
    ISSUE4(0, 0);
    asm volatile("cp.async.commit_group;");
    ISSUE4(1, 32);
    asm volatile("cp.async.commit_group;");

    for (int it = 0; it < KT; it++) {
        asm volatile("cp.async.wait_group 1;");
        __syncthreads();
        if (it + 2 < KT) ISSUE4((it + 2) % 3, (it + 2) * 32);
        asm volatile("cp.async.commit_group;");

        const int st = it % 3;
        const char* Asb = (const char*)dsm + st * A4_STAGE_B;
        const char* Bsb = (const char*)dsm + B4_OFF_B + st * B4_STAGE_B;
#pragma unroll
        for (int c = 0; c < 2; c++) {
            uint32_t af[4][4], bf[4][2];
#pragma unroll
            for (int mi = 0; mi < 4; mi++) {
                int m0 = wr * 64 + mi * 16 + tg;
                const char* p0 = Asb + m0 * 80 + c * 32 + tq * 4;
                const char* p1 = Asb + (m0 + 8) * 80 + c * 32 + tq * 4;
                af[mi][0] = *(const uint32_t*)p0;
                af[mi][1] = *(const uint32_t*)p1;
                af[mi][2] = *(const uint32_t*)(p0 + 16);
                af[mi][3] = *(const uint32_t*)(p1 + 16);
            }
#pragma unroll
            for (int ni = 0; ni < 4; ni++) {
                int n0 = wc * 32 + ni * 8 + tg;
                const char* pb = Bsb + (c * 8 + tq) * 544 + n0 * 4;
                bf[ni][0] = *(const uint32_t*)pb;
                bf[ni][1] = *(const uint32_t*)(pb + 4 * 544);
            }
#pragma unroll
            for (int mi = 0; mi < 4; mi++)
#pragma unroll
                for (int ni = 0; ni < 4; ni++)
                    mma_f16(acc[mi][ni], af[mi], bf[ni]);
        }
    }
#undef ISSUE4

#pragma unroll
    for (int mi = 0; mi < 4; mi++) {
        int r0 = blockIdx.y * 128 + wr * 64 + mi * 16 + tg;
        int r1 = r0 + 8;
#pragma unroll
        for (int ni = 0; ni < 4; ni++) {
            int cc = blockIdx.x * 128 + wc * 32 + ni * 8 + tq * 2;
            float v00 = acc[mi][ni][0], v01 = acc[mi][ni][1];
            float v10 = acc[mi][ni][2], v11 = acc[mi][ni][3];
            if (bz) {
                float b0v = bz[cc], b1v = bz[cc + 1];
                v00 += b0v; v01 += b1v; v10 += b0v; v11 += b1v;
            }
            if (EPI == 1) {
                v00 = fmaxf(v00, 0.f); v01 = fmaxf(v01, 0.f);
                v10 = fmaxf(v10, 0.f); v11 = fmaxf(v11, 0.f);
            }
            if (EPI == 2) {
                float2 e0 = *(const float2*)&res[(size_t)r0 * N + cc];
                float2 e1 = *(const float2*)&res[(size_t)r1 * N + cc];
                v00 += e0.x; v01 += e0.y; v10 += e1.x; v11 += e1.y;
            }
            if (EPI == 3) {
                int gs0 = z * M + r0, gs1 = z * M + r1;
                int i0 = sidx[gs0], i1 = sidx[gs1];
                if (i0 >= 0) {
                    float g = sgate[gs0];
                    atomicAdd(&scat[(size_t)i0 * N + cc],     g * v00);
                    atomicAdd(&scat[(size_t)i0 * N + cc + 1], g * v01);
                }
                if (i1 >= 0) {
                    float g = sgate[gs1];
                    atomicAdd(&scat[(size_t)i1 * N + cc],     g * v10);
                    atomicAdd(&scat[(size_t)i1 * N + cc + 1], g * v11);
                }
            } else if (OUTH) {
                __half* Ch = (__half*)Cout + (size_t)z * sC;
                *(__half2*)&Ch[(size_t)r0 * N + cc] = __floats2half2_rn(v00, v01);
                *(__half2*)&Ch[(size_t)r1 * N + cc] = __floats2half2_rn(v10, v11);
            } else {
                float* Cf = (float*)Cout + (size_t)z * sC;
                *(float2*)&Cf[(size_t)r0 * N + cc] = make_float2(v00, v01);
                *(float2*)&Cf[(size_t)r1 * N + cc] = make_float2(v10, v11);
            }
        }
    }
}

// fp16 tensor-core flash attention. K smem [key][dim], V smem transposed [dim][key].
// P C-frag IS the fp16 A-frag layout -> zero shuffles in PV.
__global__ __launch_bounds__(256, 2) void attn_f16_kernel(const float* __restrict__ qkv,
                                                          __half* __restrict__ aout) {
    __shared__ __half Ks[64][72];
    __shared__ __half Vt[64][72];
    const int bh = blockIdx.y, b = bh >> 4, h = bh & 15;
    const int tid = threadIdx.x, lane = tid & 31, w = tid >> 5;
    const int tg = lane >> 2, tq = lane & 3;
    const int q0 = blockIdx.x * 128 + w * 16;
    const float* qbase = qkv + (size_t)b * TSEQ * 3072 + h * 64;

    // Q fp16 a-frags (scale folded): qa[kc][0]=row tg k(2tq,2tq+1); [1]=row tg+8; [2],[3]=+8 dims
    uint32_t qa[4][4];
    {
        const float* qr0 = qbase + (size_t)(q0 + tg) * 3072;
        const float* qr1 = qbase + (size_t)(q0 + tg + 8) * 3072;
#pragma unroll
        for (int kc = 0; kc < 4; kc++) {
            int d0 = kc * 16 + 2 * tq;
            qa[kc][0] = packh2(qr0[d0] * 0.125f,     qr0[d0 + 1] * 0.125f);
            qa[kc][1] = packh2(qr1[d0] * 0.125f,     qr1[d0 + 1] * 0.125f);
            qa[kc][2] = packh2(qr0[d0 + 8] * 0.125f, qr0[d0 + 9] * 0.125f);
            qa[kc][3] = packh2(qr1[d0 + 8] * 0.125f, qr1[d0 + 9] * 0.125f);
        }
    }
    float oacc[8][4];
#pragma unroll
    for (int dt = 0; dt < 8; dt++)
#pragma unroll
        for (int i = 0; i < 4; i++) oacc[dt][i] = 0.f;
    float m0 = -1e30f, m1 = -1e30f, l0 = 0.f, l1 = 0.f;
    const float* kbase = qbase + 1024;
    const float* vbase = qbase + 2048;

    for (int s0 = 0; s0 < TSEQ; s0 += 64) {
        __syncthreads();
        for (int i = tid; i < 64 * 16; i += 256) {
            int j = i >> 4, dv = (i & 15) << 2;
            float4 kv = *(const float4*)(kbase + (size_t)(s0 + j) * 3072 + dv);
            float4 vv = *(const float4*)(vbase + (size_t)(s0 + j) * 3072 + dv);
            *(__half2*)&Ks[j][dv]     = __floats2half2_rn(kv.x, kv.y);
            *(__half2*)&Ks[j][dv + 2] = __floats2half2_rn(kv.z, kv.w);
            Vt[dv][j]     = __float2half(vv.x);
            Vt[dv + 1][j] = __float2half(vv.y);
            Vt[dv + 2][j] = __float2half(vv.z);
            Vt[dv + 3][j] = __float2half(vv.w);
        }
        __syncthreads();

        // S = Q K^T
        float s[8][4];
#pragma unroll
        for (int nt = 0; nt < 8; nt++) {
            s[nt][0] = s[nt][1] = s[nt][2] = s[nt][3] = 0.f;
#pragma unroll
            for (int kc = 0; kc < 4; kc++) {
                uint32_t bb[2] = {*(const uint32_t*)&Ks[nt * 8 + tg][kc * 16 + 2 * tq],
                                  *(const uint32_t*)&Ks[nt * 8 + tg][kc * 16 + 8 + 2 * tq]};
                mma_f16(s[nt], qa[kc], bb);
            }
        }
        // online softmax
        float rm0 = -1e30f, rm1 = -1e30f;
#pragma unroll
        for (int nt = 0; nt < 8; nt++) {
            rm0 = fmaxf(rm0, fmaxf(s[nt][0], s[nt][1]));
            rm1 = fmaxf(rm1, fmaxf(s[nt][2], s[nt][3]));
        }
        rm0 = fmaxf(rm0, __shfl_xor_sync(~0u, rm0, 1));
        rm0 = fmaxf(rm0, __shfl_xor_sync(~0u, rm0, 2));
        rm1 = fmaxf(rm1, __shfl_xor_sync(~0u, rm1, 1));
        rm1 = fmaxf(rm1, __shfl_xor_sync(~0u, rm1, 2));
        float mn0 = fmaxf(m0, rm0), mn1 = fmaxf(m1, rm1);
        float sc0 = __expf(m0 - mn0), sc1 = __expf(m1 - mn1);
        m0 = mn0; m1 = mn1;
        float rs0 = 0.f, rs1 = 0.f;
#pragma unroll
        for (int nt = 0; nt < 8; nt++) {
            s[nt][0] = __expf(s[nt][0] - mn0); s[nt][1] = __expf(s[nt][1] - mn0);
            s[nt][2] = __expf(s[nt][2] - mn1); s[nt][3] = __expf(s[nt][3] - mn1);
            rs0 += s[nt][0] + s[nt][1]; rs1 += s[nt][2] + s[nt][3];
        }
        rs0 += __shfl_xor_sync(~0u, rs0, 1); rs0 += __shfl_xor_sync(~0u, rs0, 2);
        rs1 += __shfl_xor_sync(~0u, rs1, 1); rs1 += __shfl_xor_sync(~0u, rs1, 2);
        l0 = l0 * sc0 + rs0; l1 = l1 * sc1 + rs1;
#pragma unroll
        for (int dt = 0; dt < 8; dt++) {
            oacc[dt][0] *= sc0; oacc[dt][1] *= sc0;
            oacc[dt][2] *= sc1; oacc[dt][3] *= sc1;
        }
        // O += P V : P packs straight from S C-frags
#pragma unroll
        for (int c = 0; c < 4; c++) {
            uint32_t pa[4];
            pa[0] = packh2(s[2 * c][0],     s[2 * c][1]);
            pa[1] = packh2(s[2 * c][2],     s[2 * c][3]);
            pa[2] = packh2(s[2 * c + 1][0], s[2 * c + 1][1]);
            pa[3] = packh2(s[2 * c + 1][2], s[2 * c + 1][3]);
#pragma unroll
            for (int dt = 0; dt < 8; dt++) {
                uint32_t bb[2] = {*(const uint32_t*)&Vt[dt * 8 + tg][c * 16 + 2 * tq],
                                  *(const uint32_t*)&Vt[dt * 8 + tg][c * 16 + 8 + 2 * tq]};
                mma_f16(oacc[dt], pa, bb);
            }
        }
    }
    float inv0 = 1.f / l0, inv1 = 1.f / l1;
    __half* ab = aout + (size_t)b * TSEQ * CDIM;
    int t0 = q0 + tg, t1 = t0 + 8;
    int c0 = h * 64 + (t0 >> 5), r0b = (t0 & 31) * 64;
    int c1 = h * 64 + (t1 >> 5), r1b = (t1 & 31) * 64;
#pragma unroll
    for (int dt = 0; dt < 8; dt++) {
        int dd = dt * 8 + tq * 2;
        ab[(size_t)(r0b + dd) * CDIM + c0]     = __float2half(oacc[dt][0] * inv0);
        ab[(size_t)(r0b + dd + 1) * CDIM + c0] = __float2half(oacc[dt][1] * inv0);
        ab[(size_t)(r1b + dd) * CDIM + c1]     = __float2half(oacc[dt][2] * inv1);
        ab[(size_t)(r1b + dd + 1) * CDIM + c1] = __float2half(oacc[dt][3] * inv1);
    }
}

__global__ __launch_bounds__(256) void route_kernel(const float* __restrict__ wr,
                                                    const float* __restrict__ br,
                                                    const float* __restrict__ wn,
                                                    const float* __restrict__ bn) {
    int warp = threadIdx.x >> 5, lane = threadIdx.x & 31;
    int n = blockIdx.x * 8 + warp;
    const float* hp = g_h2 + (size_t)n * CDIM;
    float pr[8], pn[8];
#pragma unroll
    for (int e = 0; e < 8; e++) { pr[e] = 0.f; pn[e] = 0.f; }
    for (int c = lane; c < CDIM; c += 32) {
        float hv = hp[c];
#pragma unroll
        for (int e = 0; e < 8; e++) {
            pr[e] += hv * wr[c * 8 + e];
            pn[e] += hv * wn[c * 8 + e];
        }
    }
#pragma unroll
    for (int e = 0; e < 8; e++)
        for (int o = 16; o; o >>= 1) {
            pr[e] += __shfl_xor_sync(~0u, pr[e], o);
            pn[e] += __shfl_xor_sync(~0u, pn[e], o);
        }
    if (lane == 0)
#pragma unroll
        for (int e = 0; e < 8; e++) {
            g_logits[n * 8 + e]  = pr[e] + br[e];
            g_nlogits[n * 8 + e] = pn[e] + bn[e];
        }
}

__global__ __launch_bounds__(256) void route_post_kernel(const float* __restrict__ noise) {
    __shared__ float red[8];
    int n = blockIdx.x * blockDim.x + threadIdx.x;
    float noisy[8], mx = -1e30f;
#pragma unroll
    for (int e = 0; e < 8; e++) {
        float nl = g_nlogits[n * 8 + e];
        float sp = log1pf(expf(-fabsf(nl))) + fmaxf(nl, 0.f);
        float v = g_logits[n * 8 + e] + noise[n * 8 + e] * sp;
        noisy[e] = v; mx = fmaxf(mx, v);
    }
    float s = 0.f, p[8];
#pragma unroll
    for (int e = 0; e < 8; e++) { p[e] = expf(noisy[e] - mx); s += p[e]; }
    float inv = 1.f / s, ent = 0.f;
#pragma unroll
    for (int e = 0; e < 8; e++) { float pe = p[e] * inv; ent -= pe * logf(pe + 1e-8f); }
    int i0 = 0;
#pragma unroll
    for (int e = 1; e < 8; e++) if (noisy[e] > noisy[i0]) i0 = e;
    int i1 = (i0 == 0) ? 1 : 0;
#pragma unroll
    for (int e = 0; e < 8; e++) if (e != i0 && noisy[e] > noisy[i1]) i1 = e;
    float dgl = expf(noisy[i1] - noisy[i0]);
    float g0 = 1.f / (1.f + dgl), g1 = dgl * g0;
    g_sel[n] = i0 | (i1 << 8);
    g_gate[2 * n] = g0; g_gate[2 * n + 1] = g1;
    float es = ent;
    for (int o = 16; o; o >>= 1) es += __shfl_xor_sync(~0u, es, o);
    int lane = threadIdx.x & 31, wid = threadIdx.x >> 5;
    if (lane == 0) red[wid] = es;
    __syncthreads();
    if (threadIdx.x < 8) {
        float t = red[threadIdx.x];
        for (int o = 4; o; o >>= 1) t += __shfl_xor_sync(0xffu, t, o);
        if (threadIdx.x == 0) atomicAdd(&g_ent, t);
    }
}

__global__ void assign_kernel() {
    int lane = threadIdx.x;
    int cnt[8];
#pragma unroll
    for (int e = 0; e < 8; e++) cnt[e] = 0;
    unsigned lt = (1u << lane) - 1u;
    for (int n0 = 0; n0 < NTOK; n0 += 32) {
        int n = n0 + lane;
        int sel = g_sel[n];
        int e0 = sel & 255, e1 = (sel >> 8) & 255;
        float g0 = g_gate[2 * n], g1 = g_gate[2 * n + 1];
#pragma unroll
        for (int e = 0; e < 8; e++) {
            bool mt = (e0 == e) || (e1 == e);
            unsigned mask = __ballot_sync(~0u, mt);
            if (mt) {
                int r = cnt[e] + __popc(mask & lt);
                if (r < CAP) {
                    g_slot_idx[e * CAP + r]  = n;
                    g_slot_gate[e * CAP + r] = (e0 == e) ? g0 : g1;
                }
            }
            cnt[e] += __popc(mask);
        }
    }
#pragma unroll
    for (int e = 0; e < 8; e++)
        for (int r = cnt[e] + lane; r < CAP; r += 32) {
            g_slot_idx[e * CAP + r]  = -1;
            g_slot_gate[e * CAP + r] = 0.f;
        }
}

__global__ void final_kernel(float* __restrict__ out, int out_size) {
    int i = blockIdx.x * blockDim.x + threadIdx.x;
    if (i < NTOK * CDIM) out[i] = g_x2[i] + g_upd[i];
    else if (i < out_size) out[i] = g_ent * (1.f / NTOK);
}

static void* symp(const void* s) { void* p = nullptr; cudaGetSymbolAddress(&p, s); return p; }

extern "C" void kernel_launch(void* const* d_in, const int* in_sizes, int n_in,
                              void* d_out, int out_size) {
    const float* x       = (const float*)d_in[0];
    const float* noise   = (const float*)d_in[1];
    const float* gamma1  = (const float*)d_in[2];
    const float* beta1   = (const float*)d_in[3];
    const float* gamma2  = (const float*)d_in[4];
    const float* beta2   = (const float*)d_in[5];
    const float* w_qkv   = (const float*)d_in[6];
    const float* w_out   = (const float*)d_in[7];
    const float* w_route = (const float*)d_in[8];
    const float* b_route = (const float*)d_in[9];
    const float* w_noise = (const float*)d_in[10];
    const float* b_noise = (const float*)d_in[11];
    const float* w1      = (const float*)d_in[12];
    const float* b1      = (const float*)d_in[13];
    const float* w2      = (const float*)d_in[14];
    const float* b2      = (const float*)d_in[15];
    float* out = (float*)d_out;

    __half*  p_h1h   = (__half*)symp(g_h1h);
    float*   p_qkv   = (float*)symp(g_qkv);
    __half*  p_attnh = (__half*)symp(g_attnh);
    float*   p_x2    = (float*)symp(g_x2);
    float*   p_h2    = (float*)symp(g_h2);
    __half*  p_h2h   = (__half*)symp(g_h2h);
    __half*  p_hidh  = (__half*)symp(g_hidh);
    float*   p_upd   = (float*)symp(g_upd);
    __half*  p_zeroh = (__half*)symp(g_zeroh);
    __half2* p_wqkvh = (__half2*)symp(g_wqkvh);
    __half2* p_wouth = (__half2*)symp(g_wouth);
    __half2* p_w1h   = (__half2*)symp(g_w1h);
    __half2* p_w2h   = (__half2*)symp(g_w2h);
    int*     p_sidx  = (int*)symp(g_slot_idx);
    float*   p_sg    = (float*)symp(g_slot_gate);

    static int smem_set = 0;
    if (!smem_set) {
        cudaFuncSetAttribute(tgemm4_kernel<0, false, false>, cudaFuncAttributeMaxDynamicSharedMemorySize, SMEM4_BYTES);
        cudaFuncSetAttribute(tgemm4_kernel<2, false, false>, cudaFuncAttributeMaxDynamicSharedMemorySize, SMEM4_BYTES);
        cudaFuncSetAttribute(tgemm4_kernel<1, true,  true >, cudaFuncAttributeMaxDynamicSharedMemorySize, SMEM4_BYTES);
        cudaFuncSetAttribute(tgemm4_kernel<3, false, false>, cudaFuncAttributeMaxDynamicSharedMemorySize, SMEM4_BYTES);
        smem_set = 1;
    }

    zero_kernel<<<NTOK * CDIM / 4 / 256, 256>>>();
    convw_kernel<<<dim3(512 * 3072 / 4 / 256, 1, 1), 256>>>(w_qkv, p_wqkvh, 512, 3072);
    convw_kernel<<<dim3(512 * 1024 / 4 / 256, 1, 1), 256>>>(w_out, p_wouth, 512, 1024);
    convw_kernel<<<dim3(512 * DFF / 4 / 256, 1, NEXP), 256>>>(w1, p_w1h, 512, DFF);
    convw_kernel<<<dim3(2048 * CDIM / 4 / 256, 1, NEXP), 256>>>(w2, p_w2h, 2048, CDIM);

    ln_kernel<<<NTOK, 256>>>(x, gamma1, beta1, nullptr, p_h1h);
    tgemm4_kernel<0, false, false><<<dim3(3072 / 128, 4096 / 128, 1), 256, SMEM4_BYTES>>>(
        p_h1h, p_wqkvh, p_qkv, 4096, 3072, 1024,
        nullptr, nullptr, nullptr, nullptr, nullptr, p_zeroh, 0, 0, 0, 0);
    attn_f16_kernel<<<dim3(TSEQ / 128, BSZ * 16), 256>>>(p_qkv, p_attnh);
    tgemm4_kernel<2, false, false><<<dim3(1024 / 128, 4096 / 128, 1), 256, SMEM4_BYTES>>>(
        p_attnh, p_wouth, p_x2, 4096, 1024, 1024,
        nullptr, x, nullptr, nullptr, nullptr, p_zeroh, 0, 0, 0, 0);
    ln_kernel<<<NTOK, 256>>>(p_x2, gamma2, beta2, p_h2, p_h2h);
    route_kernel<<<NTOK / 8, 256>>>(w_route, b_route, w_noise, b_noise);
    route_post_kernel<<<NTOK / 256, 256>>>(noise);
    assign_kernel<<<1, 32>>>();
    tgemm4_kernel<1, true, true><<<dim3(DFF / 128, 1024 / 128, NEXP), 256, SMEM4_BYTES>>>(
        p_h2h, p_w1h, p_hidh, 1024, DFF, 1024,
        b1, nullptr, p_sidx, nullptr, nullptr, p_zeroh,
        0, (size_t)512 * DFF, (size_t)CAP * DFF, DFF);
    tgemm4_kernel<3, false, false><<<dim3(1024 / 128, 1024 / 128, NEXP), 256, SMEM4_BYTES>>>(
        p_hidh, p_w2h, nullptr, 1024, 1024, 4096,
        b2, nullptr, p_sidx, p_sg, p_upd, p_zeroh,
        (size_t)CAP * DFF, (size_t)2048 * CDIM, 0, CDIM);
    final_kernel<<<(out_size + 255) / 256, 256>>>(out, out_size);
}